// round 12
// baseline (speedup 1.0000x reference)
#include <cuda_runtime.h>
#include <cuda_fp16.h>

#define BB 256
#define TT 256
#define HH 16
#define DD 88
#define NG 30
#define L2E 1.4426950408889634f
#define LOG16F 2.7725887222397811f

// dynamic smem layout (float offsets)
#define OFF_LUT 0                       // 30*64*20 = 38400 floats (153.6 KB)
#define OFF_E   38400                   // 2*256*20 = 10240 (stride-20)
#define OFF_ME  48640                   // 512
#define OFF_PK  49152                   // u32: 2*772 = 1544
#define OFF_FLG 50696                   // u32: 16
#define OFF_VW  50712                   // 32
#define OFF_CB  50744                   // 2
#define SMEM_FLOATS 50746
#define SMEM_BYTES (SMEM_FLOATS * 4)

__device__ float g_LUT[NG * 64 * 20];   // padded like smem layout
__device__ float g_part[BB];
__device__ unsigned int g_ticket;       // zero-init; wraps via atomicInc

#define ADD_F32X2(out, a, b) \
    asm("add.rn.f32x2 %0, %1, %2;" : "=l"(out) : "l"(a), "l"(b))

__device__ __forceinline__ unsigned pack4(float4 v) {
    return (v.x > 0.5f ? 1u : 0u) | (v.y > 0.5f ? 2u : 0u) |
           (v.z > 0.5f ? 4u : 0u) | (v.w > 0.5f ? 8u : 0u);
}
__device__ __forceinline__ float warp16_max(float m) {
    m = fmaxf(m, __shfl_xor_sync(0xffffffffu, m, 8));
    m = fmaxf(m, __shfl_xor_sync(0xffffffffu, m, 4));
    m = fmaxf(m, __shfl_xor_sync(0xffffffffu, m, 2));
    m = fmaxf(m, __shfl_xor_sync(0xffffffffu, m, 1));
    return m;
}
__device__ __forceinline__ float warp16_sum(float s) {
    s += __shfl_xor_sync(0xffffffffu, s, 8);
    s += __shfl_xor_sync(0xffffffffu, s, 4);
    s += __shfl_xor_sync(0xffffffffu, s, 2);
    s += __shfl_xor_sync(0xffffffffu, s, 1);
    return s;
}

// ---------------------------------------------------------------------------
// Pre-kernel: build the padded 3-d LUT in gmem (one block per d-group g).
// LUT[g][combo][h] = sum_{k<3} logterm(c_k, 3g+k, h),
//   c_k = ((combo>>(3+k))&1)<<1 | ((combo>>k)&1)
// ---------------------------------------------------------------------------
__global__ void build_lut(const float* __restrict__ py) {
    __shared__ float sW[4][3][16];
    const int g = blockIdx.x;
    const int tid = threadIdx.x;
    if (tid < 192) {
        int h = tid & 15;
        int k = (tid >> 4) % 3;
        int c = tid / 48;
        int d = 3 * g + k;
        float v = 0.f;
        if (d < DD) {
            int yp = c >> 1, yb = c & 1;
            float p = py[(h * 2 + yp) * DD + d];
            v = yb ? __logf(p) : __logf(1.0f - p);
        }
        sW[c][k][h] = v;
    }
    __syncthreads();
    for (int e = tid; e < 64 * 16; e += blockDim.x) {
        int h = e & 15;
        int combo = e >> 4;
        int c0 = (((combo >> 3) & 1) << 1) | (combo & 1);
        int c1 = (((combo >> 4) & 1) << 1) | ((combo >> 1) & 1);
        int c2 = (((combo >> 5) & 1) << 1) | ((combo >> 2) & 1);
        g_LUT[(g * 64 + combo) * 20 + h] = sW[c0][0][h] + sW[c1][1][h] + sW[c2][2][h];
    }
}

// ---------------------------------------------------------------------------
__global__ void __launch_bounds__(1024, 1)
fused_hmm(const float* __restrict__ seq, const int* __restrict__ lengths,
          const float* __restrict__ px, float* __restrict__ out) {
    extern __shared__ __align__(16) float smem[];
    float*    sLUT = smem + OFF_LUT;
    float*    sE   = smem + OFF_E;      // [q][t][20] (only h<16 used)
    float*    sMe  = smem + OFF_ME;     // [q][256]
    unsigned* sPack = reinterpret_cast<unsigned*>(smem + OFF_PK);   // [q][257][3]
    volatile unsigned* sFlag = reinterpret_cast<volatile unsigned*>(smem + OFF_FLG);
    float*    sVW  = smem + OFF_VW;     // [q][16]
    float*    sCB  = smem + OFF_CB;     // [q]

    const int tid  = threadIdx.x;
    const int lane = tid & 31;
    const int wid  = tid >> 5;          // 0..31

    if (tid < 3) { sPack[tid] = 0u; sPack[772 + tid] = 0u; }
    if (tid < 16) sFlag[tid] = 0u;

    // ---- copy precomputed LUT gmem -> smem (L2-resident, float4 stream) ----
    {
        const float4* src = reinterpret_cast<const float4*>(g_LUT);
        float4* dst = reinterpret_cast<float4*>(sLUT);
#pragma unroll
        for (int rep = 0; rep < 10; rep++) {
            int u = tid + rep * 1024;
            if (u < NG * 64 * 5) dst[u] = __ldg(src + u);
        }
    }

    // ---- ballot-free bit-pack for both batches (only t < L) ----
#pragma unroll
    for (int rep = 0; rep < 2; rep++) {
        int idx = tid + rep * 1024;
        if (idx < 2 * TT * 3) {
            int q = (idx >= TT * 3) ? 1 : 0;
            int r = idx - q * (TT * 3);
            int t = r / 3;
            int w = r - t * 3;
            int Lq = lengths[blockIdx.x * 2 + q];
            if (t < Lq) {
                const float* sb = seq + ((size_t)(blockIdx.x * 2 + q)) * TT * DD;
                const float4* src = reinterpret_cast<const float4*>(sb + t * DD + w * 32);
                float4 v0 = src[0], v1 = src[1], v2 = src[2];
                float4 v3 = src[3], v4 = src[4], v5 = src[5];
                unsigned bits = pack4(v0) | (pack4(v1) << 4) | (pack4(v2) << 8) |
                                (pack4(v3) << 12) | (pack4(v4) << 16) | (pack4(v5) << 20);
                if (w < 2) {
                    float4 v6 = src[6], v7 = src[7];
                    bits |= (pack4(v6) << 24) | (pack4(v7) << 28);
                }
                sPack[q * 772 + (t + 1) * 3 + w] = bits;
            }
        }
    }
    __syncthreads();

    // ---- emit: warp w<16 covers batch q=w>>3, t in [(w&7)*32, +32); 1 thread/t ----
    if (wid < 16) {
        const int q = wid >> 3;
        const int t = (wid & 7) * 32 + lane;
        const int L = lengths[blockIdx.x * 2 + q];
        if (t < L) {
            const unsigned* pk = &sPack[q * 772 + t * 3];
            unsigned pw[4], yw[4];
            pw[0] = pk[0]; pw[1] = pk[1]; pw[2] = pk[2]; pw[3] = 0u;
            yw[0] = pk[3]; yw[1] = pk[4]; yw[2] = pk[5]; yw[3] = 0u;

            unsigned long long acc2[8];
#pragma unroll
            for (int k = 0; k < 8; k++) acc2[k] = 0ull;

#pragma unroll
            for (int g = 0; g < NG; g++) {
                const int bp = 3 * g;
                const int wi = bp >> 5;
                const int sh = bp & 31;
                unsigned yb = __funnelshift_r(yw[wi], yw[wi + 1], sh) & 7u;
                unsigned pb = __funnelshift_r(pw[wi], pw[wi + 1], sh) & 7u;
                unsigned combo = yb | (pb << 3);
                const ulonglong2* p2v = reinterpret_cast<const ulonglong2*>(
                    sLUT + g * 1280 + combo * 20);
                ulonglong2 q0 = p2v[0], q1 = p2v[1], q2 = p2v[2], q3 = p2v[3];
                ADD_F32X2(acc2[0], acc2[0], q0.x);
                ADD_F32X2(acc2[1], acc2[1], q0.y);
                ADD_F32X2(acc2[2], acc2[2], q1.x);
                ADD_F32X2(acc2[3], acc2[3], q1.y);
                ADD_F32X2(acc2[4], acc2[4], q2.x);
                ADD_F32X2(acc2[5], acc2[5], q2.y);
                ADD_F32X2(acc2[6], acc2[6], q3.x);
                ADD_F32X2(acc2[7], acc2[7], q3.y);
            }

            float acc[16];
#pragma unroll
            for (int k = 0; k < 8; k++) {
                unsigned lo, hi;
                asm("mov.b64 {%0, %1}, %2;" : "=r"(lo), "=r"(hi) : "l"(acc2[k]));
                acc[2 * k]     = __uint_as_float(lo);
                acc[2 * k + 1] = __uint_as_float(hi);
            }
            float m = acc[0];
#pragma unroll
            for (int h = 1; h < 16; h++) m = fmaxf(m, acc[h]);

            // exp via f16x2 MUFU (2 exps per op); convert back to f32 for scan
            float* eo = sE + q * 5120 + t * 20;
#pragma unroll
            for (int h4 = 0; h4 < 4; h4++) {
                float x0 = (acc[h4 * 4 + 0] - m) * L2E;
                float x1 = (acc[h4 * 4 + 1] - m) * L2E;
                float x2 = (acc[h4 * 4 + 2] - m) * L2E;
                float x3 = (acc[h4 * 4 + 3] - m) * L2E;
                unsigned p01, p23, e01, e23;
                asm("cvt.rn.f16x2.f32 %0, %1, %2;" : "=r"(p01) : "f"(x1), "f"(x0));
                asm("cvt.rn.f16x2.f32 %0, %1, %2;" : "=r"(p23) : "f"(x3), "f"(x2));
                asm("ex2.approx.f16x2 %0, %1;" : "=r"(e01) : "r"(p01));
                asm("ex2.approx.f16x2 %0, %1;" : "=r"(e23) : "r"(p23));
                float2 f01 = __half22float2(*reinterpret_cast<__half2*>(&e01));
                float2 f23 = __half22float2(*reinterpret_cast<__half2*>(&e23));
                float4 ev;
                ev.x = f01.x; ev.y = f01.y; ev.z = f23.x; ev.w = f23.y;
                *reinterpret_cast<float4*>(eo + h4 * 4) = ev;
            }
            sMe[q * 256 + t] = m;
        }
        __threadfence_block();
        __syncwarp();
        if (lane == 0) sFlag[wid] = 1u;   // flag index = q*8 + chunk
    }

    // ---- bidirectional scan: warps 0..3 = (batch q = wid>>1, dir = wid&1) ----
    if (wid < 4) {
        const int q = wid >> 1;
        const int dir = wid & 1;
        const int bGlob = blockIdx.x * 2 + q;
        const int L = lengths[bGlob];
        const int mid = L >> 1;
        const int j = lane & 15;
        const float* sEq = sE + q * 5120;
        const float* sMq = sMe + q * 256;
        volatile unsigned* flg = sFlag + q * 8;

        if (dir == 0) {
            // forward: u = alpha0^T prod_{t<mid} P diag(e_t)
            float Pc[16];
#pragma unroll
            for (int i = 0; i < 16; i++) Pc[i] = px[i * 16 + j];

            float a = (j == 0) ? 1.f : 0.f;
            float C = 0.f;
            int t = 0;
            for (int c = 0; c * 32 < mid; c++) {
                while (flg[c] == 0u) __nanosleep(32);
                __threadfence_block();
                int t1 = (c * 32 + 32 < mid) ? (c * 32 + 32) : mid;
                float ec = sEq[t * 20 + j];
                float mc = sMq[t];
                for (; t < t1; t++) {
                    float ecn = 1.f, mcn = 0.f;
                    if (t + 1 < t1) {
                        ecn = sEq[(t + 1) * 20 + j];
                        mcn = sMq[t + 1];
                    }
                    float a0 = 0.f, a1 = 0.f, a2 = 0.f, a3 = 0.f;
#pragma unroll
                    for (int i = 0; i < 16; i += 4) {
                        a0 = fmaf(__shfl_sync(0xffffffffu, a, i),     Pc[i],     a0);
                        a1 = fmaf(__shfl_sync(0xffffffffu, a, i + 1), Pc[i + 1], a1);
                        a2 = fmaf(__shfl_sync(0xffffffffu, a, i + 2), Pc[i + 2], a2);
                        a3 = fmaf(__shfl_sync(0xffffffffu, a, i + 3), Pc[i + 3], a3);
                    }
                    a = ((a0 + a1) + (a2 + a3)) * ec;
                    C += mc;
                    if ((t & 15) == 15) {
                        float m = warp16_max(a);
                        a = __fdividef(a, m);
                        C += __logf(m);
                    }
                    ec = ecn;
                    mc = mcn;
                }
            }

            asm volatile("bar.sync %0, %1;" :: "r"(1 + q), "r"(64) : "memory");

            float dv = warp16_sum(a * sVW[q * 16 + j]);
            float res = C + sCB[q] + logf(dv) + (float)(TT - L) * LOG16F;

            // ---- in-kernel deterministic final reduction (last result) ----
            unsigned lastFlag = 0;
            if (lane == 0) {
                g_part[bGlob] = res;
                __threadfence();
                unsigned old = atomicInc(&g_ticket, BB - 1);   // wraps at 255
                lastFlag = (old == BB - 1) ? 1u : 0u;
            }
            lastFlag = __shfl_sync(0xffffffffu, lastFlag, 0);
            if (lastFlag) {
                __threadfence();
                float s2 = 0.f;
#pragma unroll
                for (int i = 0; i < BB / 32; i++)
                    s2 += *((volatile float*)&g_part[i * 32 + lane]);
                s2 += __shfl_xor_sync(0xffffffffu, s2, 16);
                s2 += __shfl_xor_sync(0xffffffffu, s2, 8);
                s2 += __shfl_xor_sync(0xffffffffu, s2, 4);
                s2 += __shfl_xor_sync(0xffffffffu, s2, 2);
                s2 += __shfl_xor_sync(0xffffffffu, s2, 1);
                if (lane == 0) out[0] = s2;
            }
        } else {
            // backward: w = prod_{t>=mid} (P diag(e_t)) * ones, descending
            float Pr[16];
#pragma unroll
            for (int i = 0; i < 16; i++) Pr[i] = px[j * 16 + i];

            float w = 1.f;
            float C = 0.f;
            int cnt = 0;
            int cLo = mid >> 5;
            for (int c = (L - 1) >> 5; c >= cLo; c--) {
                while (flg[c] == 0u) __nanosleep(32);
                __threadfence_block();
                int tHi = ((c * 32 + 32 < L) ? (c * 32 + 32) : L) - 1;
                int tLo = (c * 32 > mid) ? (c * 32) : mid;
                float ec = sEq[tHi * 20 + j];
                float mc = sMq[tHi];
                for (int t = tHi; t >= tLo; t--) {
                    float ecn = 1.f, mcn = 0.f;
                    if (t - 1 >= tLo) {
                        ecn = sEq[(t - 1) * 20 + j];
                        mcn = sMq[t - 1];
                    }
                    float s = w * ec;
                    float a0 = 0.f, a1 = 0.f, a2 = 0.f, a3 = 0.f;
#pragma unroll
                    for (int i = 0; i < 16; i += 4) {
                        a0 = fmaf(__shfl_sync(0xffffffffu, s, i),     Pr[i],     a0);
                        a1 = fmaf(__shfl_sync(0xffffffffu, s, i + 1), Pr[i + 1], a1);
                        a2 = fmaf(__shfl_sync(0xffffffffu, s, i + 2), Pr[i + 2], a2);
                        a3 = fmaf(__shfl_sync(0xffffffffu, s, i + 3), Pr[i + 3], a3);
                    }
                    w = (a0 + a1) + (a2 + a3);
                    C += mc;
                    cnt++;
                    if ((cnt & 7) == 0) {
                        float m = warp16_max(w);
                        w = __fdividef(w, m);
                        C += __logf(m);
                    }
                    ec = ecn;
                    mc = mcn;
                }
            }
            if (lane < 16) sVW[q * 16 + lane] = w;
            if (lane == 0) sCB[q] = C;
            asm volatile("bar.sync %0, %1;" :: "r"(1 + q), "r"(64) : "memory");
        }
    }
}

extern "C" void kernel_launch(void* const* d_in, const int* in_sizes, int n_in,
                              void* d_out, int out_size) {
    const float* seq     = (const float*)d_in[0];  // (B,T,D) float32
    const int*   lengths = (const int*)  d_in[1];  // (B,)    int32
    const float* probs_x = (const float*)d_in[2];  // (H,H)   float32
    const float* probs_y = (const float*)d_in[3];  // (H,2,D) float32

    build_lut<<<NG, 256>>>(probs_y);
    cudaFuncSetAttribute(fused_hmm, cudaFuncAttributeMaxDynamicSharedMemorySize, SMEM_BYTES);
    fused_hmm<<<BB / 2, 1024, SMEM_BYTES>>>(seq, lengths, probs_x, (float*)d_out);
}

// round 13
// speedup vs baseline: 1.0589x; 1.0589x over previous
#include <cuda_runtime.h>
#include <cuda_fp16.h>

#define BB 256
#define TT 256
#define HH 16
#define DD 88
#define NG 30
#define L2E 1.4426950408889634f
#define LOG16F 2.7725887222397811f
#define FULL 0xffffffffu

// dynamic smem layout (float offsets)
#define OFF_LUT 0                       // 30*64*20 = 38400 floats (153.6 KB)
#define OFF_E   38400                   // 2*256*20 = 10240 (stride-20)
#define OFF_ME  48640                   // 512
#define OFF_PK  49152                   // u32: 2*772 = 1544
#define OFF_VW  50696                   // 32
#define OFF_CB  50728                   // 2
#define SMEM_FLOATS 50730
#define SMEM_BYTES (SMEM_FLOATS * 4)

__device__ float g_LUT[NG * 64 * 20];   // padded like smem layout
__device__ float g_part[BB];
__device__ unsigned int g_ticket;       // zero-init; wraps via atomicInc

#define ADD_F32X2(out, a, b) \
    asm("add.rn.f32x2 %0, %1, %2;" : "=l"(out) : "l"(a), "l"(b))

__device__ __forceinline__ unsigned pack4(float4 v) {
    return (v.x > 0.5f ? 1u : 0u) | (v.y > 0.5f ? 2u : 0u) |
           (v.z > 0.5f ? 4u : 0u) | (v.w > 0.5f ? 8u : 0u);
}
__device__ __forceinline__ float warp16_max(float m) {
    m = fmaxf(m, __shfl_xor_sync(FULL, m, 8));
    m = fmaxf(m, __shfl_xor_sync(FULL, m, 4));
    m = fmaxf(m, __shfl_xor_sync(FULL, m, 2));
    m = fmaxf(m, __shfl_xor_sync(FULL, m, 1));
    return m;
}
__device__ __forceinline__ float warp16_sum(float s) {
    s += __shfl_xor_sync(FULL, s, 8);
    s += __shfl_xor_sync(FULL, s, 4);
    s += __shfl_xor_sync(FULL, s, 2);
    s += __shfl_xor_sync(FULL, s, 1);
    return s;
}

// ---------------------------------------------------------------------------
// Pre-kernel: build the padded 3-d LUT in gmem (one block per d-group g).
// ---------------------------------------------------------------------------
__global__ void build_lut(const float* __restrict__ py) {
    __shared__ float sW[4][3][16];
    const int g = blockIdx.x;
    const int tid = threadIdx.x;
    if (tid < 192) {
        int h = tid & 15;
        int k = (tid >> 4) % 3;
        int c = tid / 48;
        int d = 3 * g + k;
        float v = 0.f;
        if (d < DD) {
            int yp = c >> 1, yb = c & 1;
            float p = py[(h * 2 + yp) * DD + d];
            v = yb ? __logf(p) : __logf(1.0f - p);
        }
        sW[c][k][h] = v;
    }
    __syncthreads();
    for (int e = tid; e < 64 * 16; e += blockDim.x) {
        int h = e & 15;
        int combo = e >> 4;
        int c0 = (((combo >> 3) & 1) << 1) | (combo & 1);
        int c1 = (((combo >> 4) & 1) << 1) | ((combo >> 1) & 1);
        int c2 = (((combo >> 5) & 1) << 1) | ((combo >> 2) & 1);
        g_LUT[(g * 64 + combo) * 20 + h] = sW[c0][0][h] + sW[c1][1][h] + sW[c2][2][h];
    }
}

// ---------------------------------------------------------------------------
__global__ void __launch_bounds__(1024, 1)
fused_hmm(const float* __restrict__ seq, const int* __restrict__ lengths,
          const float* __restrict__ px, float* __restrict__ out) {
    extern __shared__ __align__(16) float smem[];
    float*    sLUT = smem + OFF_LUT;
    float*    sE   = smem + OFF_E;      // [q][t][20] (only h<16 used)
    float*    sMe  = smem + OFF_ME;     // [q][256]
    unsigned* sPack = reinterpret_cast<unsigned*>(smem + OFF_PK);   // [q][257][3]
    float*    sVW  = smem + OFF_VW;     // [q][16]
    float*    sCB  = smem + OFF_CB;     // [q]

    const int tid  = threadIdx.x;
    const int lane = tid & 31;
    const int wid  = tid >> 5;          // 0..31

    if (tid < 3) { sPack[tid] = 0u; sPack[772 + tid] = 0u; }

    // ---- copy precomputed LUT gmem -> smem (L2-resident, float4 stream) ----
    {
        const float4* src = reinterpret_cast<const float4*>(g_LUT);
        float4* dst = reinterpret_cast<float4*>(sLUT);
#pragma unroll
        for (int rep = 0; rep < 10; rep++) {
            int u = tid + rep * 1024;
            if (u < NG * 64 * 5) dst[u] = __ldg(src + u);
        }
    }

    // ---- ballot-free bit-pack for both batches (only t < L) ----
#pragma unroll
    for (int rep = 0; rep < 2; rep++) {
        int idx = tid + rep * 1024;
        if (idx < 2 * TT * 3) {
            int q = (idx >= TT * 3) ? 1 : 0;
            int r = idx - q * (TT * 3);
            int t = r / 3;
            int w = r - t * 3;
            int Lq = lengths[blockIdx.x * 2 + q];
            if (t < Lq) {
                const float* sb = seq + ((size_t)(blockIdx.x * 2 + q)) * TT * DD;
                const float4* src = reinterpret_cast<const float4*>(sb + t * DD + w * 32);
                float4 v0 = src[0], v1 = src[1], v2 = src[2];
                float4 v3 = src[3], v4 = src[4], v5 = src[5];
                unsigned bits = pack4(v0) | (pack4(v1) << 4) | (pack4(v2) << 8) |
                                (pack4(v3) << 12) | (pack4(v4) << 16) | (pack4(v5) << 20);
                if (w < 2) {
                    float4 v6 = src[6], v7 = src[7];
                    bits |= (pack4(v6) << 24) | (pack4(v7) << 28);
                }
                sPack[q * 772 + (t + 1) * 3 + w] = bits;
            }
        }
    }
    __syncthreads();

    // ---- emit: warp w<16 covers batch q=w>>3, t in [(w&7)*32, +32); 1 thread/t ----
    if (wid < 16) {
        const int q = wid >> 3;
        const int t = (wid & 7) * 32 + lane;
        const int L = lengths[blockIdx.x * 2 + q];
        if (t < L) {
            const unsigned* pk = &sPack[q * 772 + t * 3];
            unsigned pw[4], yw[4];
            pw[0] = pk[0]; pw[1] = pk[1]; pw[2] = pk[2]; pw[3] = 0u;
            yw[0] = pk[3]; yw[1] = pk[4]; yw[2] = pk[5]; yw[3] = 0u;

            unsigned long long acc2[8];
#pragma unroll
            for (int k = 0; k < 8; k++) acc2[k] = 0ull;

#pragma unroll
            for (int g = 0; g < NG; g++) {
                const int bp = 3 * g;
                const int wi = bp >> 5;
                const int sh = bp & 31;
                unsigned yb = __funnelshift_r(yw[wi], yw[wi + 1], sh) & 7u;
                unsigned pb = __funnelshift_r(pw[wi], pw[wi + 1], sh) & 7u;
                unsigned combo = yb | (pb << 3);
                const ulonglong2* p2v = reinterpret_cast<const ulonglong2*>(
                    sLUT + g * 1280 + combo * 20);
                ulonglong2 q0 = p2v[0], q1 = p2v[1], q2 = p2v[2], q3 = p2v[3];
                ADD_F32X2(acc2[0], acc2[0], q0.x);
                ADD_F32X2(acc2[1], acc2[1], q0.y);
                ADD_F32X2(acc2[2], acc2[2], q1.x);
                ADD_F32X2(acc2[3], acc2[3], q1.y);
                ADD_F32X2(acc2[4], acc2[4], q2.x);
                ADD_F32X2(acc2[5], acc2[5], q2.y);
                ADD_F32X2(acc2[6], acc2[6], q3.x);
                ADD_F32X2(acc2[7], acc2[7], q3.y);
            }

            float acc[16];
#pragma unroll
            for (int k = 0; k < 8; k++) {
                unsigned lo, hi;
                asm("mov.b64 {%0, %1}, %2;" : "=r"(lo), "=r"(hi) : "l"(acc2[k]));
                acc[2 * k]     = __uint_as_float(lo);
                acc[2 * k + 1] = __uint_as_float(hi);
            }
            float m = acc[0];
#pragma unroll
            for (int h = 1; h < 16; h++) m = fmaxf(m, acc[h]);

            // exp via f16x2 MUFU (2 exps per op)
            float* eo = sE + q * 5120 + t * 20;
#pragma unroll
            for (int h4 = 0; h4 < 4; h4++) {
                float x0 = (acc[h4 * 4 + 0] - m) * L2E;
                float x1 = (acc[h4 * 4 + 1] - m) * L2E;
                float x2 = (acc[h4 * 4 + 2] - m) * L2E;
                float x3 = (acc[h4 * 4 + 3] - m) * L2E;
                unsigned p01, p23, e01, e23;
                asm("cvt.rn.f16x2.f32 %0, %1, %2;" : "=r"(p01) : "f"(x1), "f"(x0));
                asm("cvt.rn.f16x2.f32 %0, %1, %2;" : "=r"(p23) : "f"(x3), "f"(x2));
                asm("ex2.approx.f16x2 %0, %1;" : "=r"(e01) : "r"(p01));
                asm("ex2.approx.f16x2 %0, %1;" : "=r"(e23) : "r"(p23));
                float2 f01 = __half22float2(*reinterpret_cast<__half2*>(&e01));
                float2 f23 = __half22float2(*reinterpret_cast<__half2*>(&e23));
                float4 ev;
                ev.x = f01.x; ev.y = f01.y; ev.z = f23.x; ev.w = f23.y;
                *reinterpret_cast<float4*>(eo + h4 * 4) = ev;
            }
            sMe[q * 256 + t] = m;
        }
    }
    __syncthreads();   // emit complete; no flags, no sleeping

    // ---- bidirectional scan: warps 0..3 = (batch q = wid>>1, dir = wid&1) ----
    // Split-half matvec: lanes (j, half=lane>>4); each half sums 8 of 16 terms,
    // one shfl_xor(16) combines. 9 SHFLs/step instead of 16.
    if (wid < 4) {
        const int q = wid >> 1;
        const int dir = wid & 1;
        const int bGlob = blockIdx.x * 2 + q;
        const int L = lengths[bGlob];
        const int mid = L >> 1;
        const int j = lane & 15;
        const int hb = (lane >> 4) * 8;     // this half's i-range base
        const float* sEq = sE + q * 5120;
        const float* sMq = sMe + q * 256;

        if (dir == 0) {
            // forward: u = alpha0^T prod_{t<mid} P diag(e_t)
            float Pc[8];
#pragma unroll
            for (int i = 0; i < 8; i++) Pc[i] = px[(hb + i) * 16 + j];

            float a = (j == 0) ? 1.f : 0.f;
            float C = 0.f;

            float ec = (mid > 0) ? sEq[j] : 1.f;
            float mc = (mid > 0) ? sMq[0] : 0.f;
#pragma unroll 2
            for (int t = 0; t < mid; t++) {
                float ecn = 1.f, mcn = 0.f;
                if (t + 1 < mid) {
                    ecn = sEq[(t + 1) * 20 + j];
                    mcn = sMq[t + 1];
                }
                float a0 = 0.f, a1 = 0.f;
#pragma unroll
                for (int i = 0; i < 8; i += 2) {
                    a0 = fmaf(__shfl_sync(FULL, a, hb + i),     Pc[i],     a0);
                    a1 = fmaf(__shfl_sync(FULL, a, hb + i + 1), Pc[i + 1], a1);
                }
                float s = a0 + a1;
                s += __shfl_xor_sync(FULL, s, 16);
                a = s * ec;
                C += mc;
                if ((t & 15) == 15) {
                    float m = warp16_max(a);
                    a = __fdividef(a, m);
                    C += __logf(m);
                }
                ec = ecn;
                mc = mcn;
            }

            asm volatile("bar.sync %0, %1;" :: "r"(1 + q), "r"(64) : "memory");

            float dv = warp16_sum(a * sVW[q * 16 + j]);
            float res = C + sCB[q] + logf(dv) + (float)(TT - L) * LOG16F;

            // ---- in-kernel deterministic final reduction (last result) ----
            unsigned lastFlag = 0;
            if (lane == 0) {
                g_part[bGlob] = res;
                __threadfence();
                unsigned old = atomicInc(&g_ticket, BB - 1);   // wraps at 255
                lastFlag = (old == BB - 1) ? 1u : 0u;
            }
            lastFlag = __shfl_sync(FULL, lastFlag, 0);
            if (lastFlag) {
                __threadfence();
                float s2 = 0.f;
#pragma unroll
                for (int i = 0; i < BB / 32; i++)
                    s2 += *((volatile float*)&g_part[i * 32 + lane]);
                s2 += __shfl_xor_sync(FULL, s2, 16);
                s2 += __shfl_xor_sync(FULL, s2, 8);
                s2 += __shfl_xor_sync(FULL, s2, 4);
                s2 += __shfl_xor_sync(FULL, s2, 2);
                s2 += __shfl_xor_sync(FULL, s2, 1);
                if (lane == 0) out[0] = s2;
            }
        } else {
            // backward: w = prod_{t>=mid} (P diag(e_t)) * ones, descending
            float Pr[8];
#pragma unroll
            for (int i = 0; i < 8; i++) Pr[i] = px[j * 16 + hb + i];

            float w = 1.f;
            float C = 0.f;
            int cnt = 0;

            float ec = (L > mid) ? sEq[(L - 1) * 20 + j] : 1.f;
            float mc = (L > mid) ? sMq[L - 1] : 0.f;
#pragma unroll 2
            for (int t = L - 1; t >= mid; t--) {
                float ecn = 1.f, mcn = 0.f;
                if (t - 1 >= mid) {
                    ecn = sEq[(t - 1) * 20 + j];
                    mcn = sMq[t - 1];
                }
                float sv = w * ec;
                float a0 = 0.f, a1 = 0.f;
#pragma unroll
                for (int i = 0; i < 8; i += 2) {
                    a0 = fmaf(__shfl_sync(FULL, sv, hb + i),     Pr[i],     a0);
                    a1 = fmaf(__shfl_sync(FULL, sv, hb + i + 1), Pr[i + 1], a1);
                }
                float s = a0 + a1;
                s += __shfl_xor_sync(FULL, s, 16);
                w = s;
                C += mc;
                cnt++;
                if ((cnt & 7) == 0) {
                    float m = warp16_max(w);
                    w = __fdividef(w, m);
                    C += __logf(m);
                }
                ec = ecn;
                mc = mcn;
            }
            if (lane < 16) sVW[q * 16 + lane] = w;
            if (lane == 0) sCB[q] = C;
            asm volatile("bar.sync %0, %1;" :: "r"(1 + q), "r"(64) : "memory");
        }
    }
}

extern "C" void kernel_launch(void* const* d_in, const int* in_sizes, int n_in,
                              void* d_out, int out_size) {
    const float* seq     = (const float*)d_in[0];  // (B,T,D) float32
    const int*   lengths = (const int*)  d_in[1];  // (B,)    int32
    const float* probs_x = (const float*)d_in[2];  // (H,H)   float32
    const float* probs_y = (const float*)d_in[3];  // (H,2,D) float32

    build_lut<<<NG, 256>>>(probs_y);
    cudaFuncSetAttribute(fused_hmm, cudaFuncAttributeMaxDynamicSharedMemorySize, SMEM_BYTES);
    fused_hmm<<<BB / 2, 1024, SMEM_BYTES>>>(seq, lengths, probs_x, (float*)d_out);
}

// round 14
// speedup vs baseline: 1.1231x; 1.0606x over previous
#include <cuda_runtime.h>
#include <cuda_fp16.h>

#define BB 256
#define TT 256
#define HH 16
#define DD 88
#define HALF_OFF 3536
#define TAB_FLOATS 7056
#define L2E 1.4426950408889634f
#define LOG16F 2.7725887222397811f
#define FULL 0xffffffffu

// dynamic smem layout (float offsets)
#define OFF_TAB 0          // 7056 (4-code padded table, two conflict-free halves)
#define OFF_E   7056       // 2*256*20 = 10240
#define OFF_ME  17296      // 512
#define OFF_PK  17808      // u32: 2*772 = 1544
#define OFF_VW  19352      // 32
#define OFF_CB  19384      // 2
#define OFF_CS  19386      // 2
#define SMEM_FLOATS 19388
#define SMEM_BYTES (SMEM_FLOATS * 4)

__device__ float g_TAB[TAB_FLOATS];
__device__ float g_part[BB];
__device__ unsigned int g_ticket;       // zero-init; wraps via atomicInc

#define ADD_F32X2(out, a, b) \
    asm("add.rn.f32x2 %0, %1, %2;" : "=l"(out) : "l"(a), "l"(b))

__device__ __forceinline__ unsigned pack4(float4 v) {
    return (v.x > 0.5f ? 1u : 0u) | (v.y > 0.5f ? 2u : 0u) |
           (v.z > 0.5f ? 4u : 0u) | (v.w > 0.5f ? 8u : 0u);
}
__device__ __forceinline__ float warp16_max(float m) {
    m = fmaxf(m, __shfl_xor_sync(FULL, m, 8));
    m = fmaxf(m, __shfl_xor_sync(FULL, m, 4));
    m = fmaxf(m, __shfl_xor_sync(FULL, m, 2));
    m = fmaxf(m, __shfl_xor_sync(FULL, m, 1));
    return m;
}
__device__ __forceinline__ float warp16_sum(float s) {
    s += __shfl_xor_sync(FULL, s, 8);
    s += __shfl_xor_sync(FULL, s, 4);
    s += __shfl_xor_sync(FULL, s, 2);
    s += __shfl_xor_sync(FULL, s, 1);
    return s;
}

// ---------------------------------------------------------------------------
// Pre-kernel: 4-code log-table in gmem (split-half padded layout; all logf here)
// ---------------------------------------------------------------------------
__global__ void build_tab4(const float* __restrict__ py) {
    int e = blockIdx.x * blockDim.x + threadIdx.x;
    if (e < 4 * DD * HH) {
        int h = e & 15;
        int rem = e >> 4;
        int d = rem % DD;
        int c = rem / DD;
        int yp = c >> 1, yb = c & 1;
        float p = py[(h * 2 + yp) * DD + d];
        float v = yb ? __logf(p) : __logf(1.0f - p);
        int addr = (d < 44) ? (d * 80 + c * 20 + h)
                            : (HALF_OFF + (d - 44) * 80 + c * 20 + h);
        g_TAB[addr] = v;
    }
}

// ---------------------------------------------------------------------------
__global__ void __launch_bounds__(1024, 1)
fused_hmm(const float* __restrict__ seq, const int* __restrict__ lengths,
          const float* __restrict__ px, float* __restrict__ out) {
    extern __shared__ __align__(16) float smem[];
    float*    sTab = smem + OFF_TAB;
    float*    sE   = smem + OFF_E;      // [q][t][20] (only h<16 used)
    float*    sMe  = smem + OFF_ME;     // [q][256], pre-zeroed
    unsigned* sPack = reinterpret_cast<unsigned*>(smem + OFF_PK);   // [q][257][3]
    float*    sVW  = smem + OFF_VW;     // [q][16]
    float*    sCB  = smem + OFF_CB;     // [q] backward renorm logs
    float*    sCS  = smem + OFF_CS;     // [q] sum of me

    const int tid  = threadIdx.x;
    const int lane = tid & 31;
    const int wid  = tid >> 5;          // 0..31

    if (tid < 3) { sPack[tid] = 0u; sPack[772 + tid] = 0u; }
    if (tid < 512) sMe[tid] = 0.f;      // me=0 for masked t (parallel sum later)

    // ---- copy precomputed table gmem -> smem ----
    {
        const float4* src = reinterpret_cast<const float4*>(g_TAB);
        float4* dst = reinterpret_cast<float4*>(sTab);
#pragma unroll
        for (int rep = 0; rep < 2; rep++) {
            int u = tid + rep * 1024;
            if (u < TAB_FLOATS / 4) dst[u] = __ldg(src + u);
        }
    }

    // ---- ballot-free bit-pack for both batches (only t < L) ----
#pragma unroll
    for (int rep = 0; rep < 2; rep++) {
        int idx = tid + rep * 1024;
        if (idx < 2 * TT * 3) {
            int q = (idx >= TT * 3) ? 1 : 0;
            int r = idx - q * (TT * 3);
            int t = r / 3;
            int w = r - t * 3;
            int Lq = lengths[blockIdx.x * 2 + q];
            if (t < Lq) {
                const float* sb = seq + ((size_t)(blockIdx.x * 2 + q)) * TT * DD;
                const float4* src = reinterpret_cast<const float4*>(sb + t * DD + w * 32);
                float4 v0 = src[0], v1 = src[1], v2 = src[2];
                float4 v3 = src[3], v4 = src[4], v5 = src[5];
                unsigned bits = pack4(v0) | (pack4(v1) << 4) | (pack4(v2) << 8) |
                                (pack4(v3) << 12) | (pack4(v4) << 16) | (pack4(v5) << 20);
                if (w < 2) {
                    float4 v6 = src[6], v7 = src[7];
                    bits |= (pack4(v6) << 24) | (pack4(v7) << 28);
                }
                sPack[q * 772 + (t + 1) * 3 + w] = bits;
            }
        }
    }
    __syncthreads();

    // ---- emit (R10 line-sharing scheme): warp w covers batch q=w>>4,
    //      t in [(w&15)*16, +16); lane pair (2k, 2k+1) = one t; half = d-range ----
    {
        const int q = wid >> 4;
        const int k = lane >> 1;
        const int half = lane & 1;      // d half: 0 -> d 0..43, 1 -> d 44..87
        const int t = (wid & 15) * 16 + k;
        const int L = lengths[blockIdx.x * 2 + q];

        const unsigned* pk = &sPack[q * 772 + t * 3];   // rows t (yprev), t+1 (y)
        unsigned p0 = pk[0], p1 = pk[1], p2 = pk[2];
        unsigned y0 = pk[3], y1 = pk[4], y2 = pk[5];

        unsigned long long Y, P;
        if (half == 0) {
            Y = (unsigned long long)y0 | ((unsigned long long)y1 << 32);
            P = (unsigned long long)p0 | ((unsigned long long)p1 << 32);
        } else {
            Y = ((unsigned long long)y1 >> 12) | ((unsigned long long)y2 << 20);
            P = ((unsigned long long)p1 >> 12) | ((unsigned long long)p2 << 20);
        }
        const float* tbase = sTab + half * HALF_OFF;

        unsigned long long acc2[8];
#pragma unroll
        for (int kk = 0; kk < 8; kk++) acc2[kk] = 0ull;

        // run unconditionally (keeps warp converged for the shfl combine);
        // garbage codes for t>=L index valid table entries and are unused
#pragma unroll 4
        for (int i = 0; i < 44; i++) {
            unsigned code = ((unsigned)((P >> i) & 1ull) << 1) | (unsigned)((Y >> i) & 1ull);
            const ulonglong2* p2v = reinterpret_cast<const ulonglong2*>(tbase + i * 80 + code * 20);
            ulonglong2 q0 = p2v[0], q1 = p2v[1], q2 = p2v[2], q3 = p2v[3];
            ADD_F32X2(acc2[0], acc2[0], q0.x);
            ADD_F32X2(acc2[1], acc2[1], q0.y);
            ADD_F32X2(acc2[2], acc2[2], q1.x);
            ADD_F32X2(acc2[3], acc2[3], q1.y);
            ADD_F32X2(acc2[4], acc2[4], q2.x);
            ADD_F32X2(acc2[5], acc2[5], q2.y);
            ADD_F32X2(acc2[6], acc2[6], q3.x);
            ADD_F32X2(acc2[7], acc2[7], q3.y);
        }

        float acc[16];
#pragma unroll
        for (int kk = 0; kk < 8; kk++) {
            unsigned lo, hi;
            asm("mov.b64 {%0, %1}, %2;" : "=r"(lo), "=r"(hi) : "l"(acc2[kk]));
            acc[2 * kk]     = __uint_as_float(lo);
            acc[2 * kk + 1] = __uint_as_float(hi);
        }
        // combine the two d-halves within the lane pair
#pragma unroll
        for (int h = 0; h < 16; h++)
            acc[h] += __shfl_xor_sync(FULL, acc[h], 1);

        if (t < L) {
            float m = acc[0];
#pragma unroll
            for (int h = 1; h < 16; h++) m = fmaxf(m, acc[h]);

            const int hb = half * 8;    // even lane writes h 0..7, odd h 8..15
            // exp via f16x2 MUFU (2 exps per op)
            float x0 = (acc[hb + 0] - m) * L2E;
            float x1 = (acc[hb + 1] - m) * L2E;
            float x2 = (acc[hb + 2] - m) * L2E;
            float x3 = (acc[hb + 3] - m) * L2E;
            float x4 = (acc[hb + 4] - m) * L2E;
            float x5 = (acc[hb + 5] - m) * L2E;
            float x6 = (acc[hb + 6] - m) * L2E;
            float x7 = (acc[hb + 7] - m) * L2E;
            unsigned pA, pB, pC, pD, eA, eB, eC, eD;
            asm("cvt.rn.f16x2.f32 %0, %1, %2;" : "=r"(pA) : "f"(x1), "f"(x0));
            asm("cvt.rn.f16x2.f32 %0, %1, %2;" : "=r"(pB) : "f"(x3), "f"(x2));
            asm("cvt.rn.f16x2.f32 %0, %1, %2;" : "=r"(pC) : "f"(x5), "f"(x4));
            asm("cvt.rn.f16x2.f32 %0, %1, %2;" : "=r"(pD) : "f"(x7), "f"(x6));
            asm("ex2.approx.f16x2 %0, %1;" : "=r"(eA) : "r"(pA));
            asm("ex2.approx.f16x2 %0, %1;" : "=r"(eB) : "r"(pB));
            asm("ex2.approx.f16x2 %0, %1;" : "=r"(eC) : "r"(pC));
            asm("ex2.approx.f16x2 %0, %1;" : "=r"(eD) : "r"(pD));
            float2 fA = __half22float2(*reinterpret_cast<__half2*>(&eA));
            float2 fB = __half22float2(*reinterpret_cast<__half2*>(&eB));
            float2 fC = __half22float2(*reinterpret_cast<__half2*>(&eC));
            float2 fD = __half22float2(*reinterpret_cast<__half2*>(&eD));
            float4 e0, e1;
            e0.x = fA.x; e0.y = fA.y; e0.z = fB.x; e0.w = fB.y;
            e1.x = fC.x; e1.y = fC.y; e1.z = fD.x; e1.w = fD.y;
            float4* eo = reinterpret_cast<float4*>(sE + q * 5120 + t * 20 + hb);
            eo[0] = e0;
            eo[1] = e1;
            if (half == 0) sMe[q * 256 + t] = m;
        }
    }
    __syncthreads();

    // ---- parallel me-sum: warps 4,5 (one per batch); joins via named barrier ----
    if (wid == 4 || wid == 5) {
        const int q = wid - 4;
        float s = 0.f;
#pragma unroll
        for (int i = 0; i < 8; i++) s += sMe[q * 256 + i * 32 + lane];
        s += __shfl_xor_sync(FULL, s, 16);
        s = warp16_sum(s);
        if (lane == 0) sCS[q] = s;
        asm volatile("bar.sync %0, %1;" :: "r"(1 + q), "r"(96) : "memory");
    }

    // ---- bidirectional scan: warps 0..3 = (batch q = wid>>1, dir = wid&1) ----
    if (wid < 4) {
        const int q = wid >> 1;
        const int dir = wid & 1;
        const int bGlob = blockIdx.x * 2 + q;
        const int L = lengths[bGlob];
        const int mid = L >> 1;
        const int j = lane & 15;
        const int hb = (lane >> 4) * 8;
        const float* sEq = sE + q * 5120;

        if (dir == 0) {
            // forward: u = alpha0^T prod_{t<mid} P diag(e_t); C = renorm logs only
            float Pc[8];
#pragma unroll
            for (int i = 0; i < 8; i++) Pc[i] = px[(hb + i) * 16 + j];

            float a = (j == 0) ? 1.f : 0.f;
            float C = 0.f;

            float ec = sEq[j];
            for (int t = 0; t < mid; t++) {
                float ecn = sEq[(t + 1) * 20 + j];   // always in-bounds; unused at t=mid-1
                float a0 = 0.f, a1 = 0.f;
#pragma unroll
                for (int i = 0; i < 8; i += 2) {
                    a0 = fmaf(__shfl_sync(FULL, a, hb + i),     Pc[i],     a0);
                    a1 = fmaf(__shfl_sync(FULL, a, hb + i + 1), Pc[i + 1], a1);
                }
                float s = a0 + a1;
                s += __shfl_xor_sync(FULL, s, 16);
                a = s * ec;
                if ((t & 15) == 15) {
                    float m = warp16_max(a);
                    a = __fdividef(a, m);
                    C += __logf(m);
                }
                ec = ecn;
            }

            asm volatile("bar.sync %0, %1;" :: "r"(1 + q), "r"(96) : "memory");

            float dv = warp16_sum(a * sVW[q * 16 + j]);
            float res = sCS[q] + C + sCB[q] + logf(dv) + (float)(TT - L) * LOG16F;

            // ---- in-kernel deterministic final reduction (last result) ----
            unsigned lastFlag = 0;
            if (lane == 0) {
                g_part[bGlob] = res;
                __threadfence();
                unsigned old = atomicInc(&g_ticket, BB - 1);   // wraps at 255
                lastFlag = (old == BB - 1) ? 1u : 0u;
            }
            lastFlag = __shfl_sync(FULL, lastFlag, 0);
            if (lastFlag) {
                __threadfence();
                float s2 = 0.f;
#pragma unroll
                for (int i = 0; i < BB / 32; i++)
                    s2 += *((volatile float*)&g_part[i * 32 + lane]);
                s2 += __shfl_xor_sync(FULL, s2, 16);
                s2 += __shfl_xor_sync(FULL, s2, 8);
                s2 += __shfl_xor_sync(FULL, s2, 4);
                s2 += __shfl_xor_sync(FULL, s2, 2);
                s2 += __shfl_xor_sync(FULL, s2, 1);
                if (lane == 0) out[0] = s2;
            }
        } else {
            // backward: w = prod_{t>=mid} (P diag(e_t)) * ones, descending
            float Pr[8];
#pragma unroll
            for (int i = 0; i < 8; i++) Pr[i] = px[j * 16 + hb + i];

            float w = 1.f;
            float C = 0.f;
            int cnt = 0;

            float ec = sEq[(L - 1) * 20 + j];
            for (int t = L - 1; t >= mid; t--) {
                float ecn = sEq[(t - 1) * 20 + j];   // in-bounds (t-1 >= mid-1 >= 0)
                float sv = w * ec;
                float a0 = 0.f, a1 = 0.f;
#pragma unroll
                for (int i = 0; i < 8; i += 2) {
                    a0 = fmaf(__shfl_sync(FULL, sv, hb + i),     Pr[i],     a0);
                    a1 = fmaf(__shfl_sync(FULL, sv, hb + i + 1), Pr[i + 1], a1);
                }
                float s = a0 + a1;
                s += __shfl_xor_sync(FULL, s, 16);
                w = s;
                cnt++;
                if ((cnt & 15) == 0) {              // shrink >= 0.04^16 >> FLT_MIN
                    float m = warp16_max(w);
                    w = __fdividef(w, m);
                    C += __logf(m);
                }
                ec = ecn;
            }
            if (lane < 16) sVW[q * 16 + lane] = w;
            if (lane == 0) sCB[q] = C;
            asm volatile("bar.sync %0, %1;" :: "r"(1 + q), "r"(96) : "memory");
        }
    }
}

extern "C" void kernel_launch(void* const* d_in, const int* in_sizes, int n_in,
                              void* d_out, int out_size) {
    const float* seq     = (const float*)d_in[0];  // (B,T,D) float32
    const int*   lengths = (const int*)  d_in[1];  // (B,)    int32
    const float* probs_x = (const float*)d_in[2];  // (H,H)   float32
    const float* probs_y = (const float*)d_in[3];  // (H,2,D) float32

    build_tab4<<<6, 1024>>>(probs_y);
    cudaFuncSetAttribute(fused_hmm, cudaFuncAttributeMaxDynamicSharedMemorySize, SMEM_BYTES);
    fused_hmm<<<BB / 2, 1024, SMEM_BYTES>>>(seq, lengths, probs_x, (float*)d_out);
}

// round 15
// speedup vs baseline: 1.2807x; 1.1404x over previous
#include <cuda_runtime.h>
#include <cuda_fp16.h>

#define BB 256
#define TT 256
#define HH 16
#define DD 88
#define NG4 22
#define L2E 1.4426950408889634f
#define LOG16F 2.7725887222397811f
#define FULL 0xffffffffu

// dynamic smem layout (32-bit word offsets)
#define OFF_LUT 0          // 22*256*8 = 45056 words (180224 B, fp16 LUT)
#define OFF_E   45056      // 2*256*16 = 8192 floats
#define OFF_ME  53248      // 512
#define OFF_PK  53760      // u32: 2*772 = 1544
#define OFF_VW  55304      // 32
#define OFF_CB  55336      // 2
#define OFF_CS  55338      // 2
#define SMEM_WORDS 55340
#define SMEM_BYTES (SMEM_WORDS * 4)

__device__ __half g_LUTH[NG4 * 256 * 16];   // [g][combo][h], fp16
__device__ float g_part[BB];
__device__ unsigned int g_ticket;            // zero-init; wraps via atomicInc

__device__ __forceinline__ unsigned pack4(float4 v) {
    return (v.x > 0.5f ? 1u : 0u) | (v.y > 0.5f ? 2u : 0u) |
           (v.z > 0.5f ? 4u : 0u) | (v.w > 0.5f ? 8u : 0u);
}
__device__ __forceinline__ float warp16_max(float m) {
    m = fmaxf(m, __shfl_xor_sync(FULL, m, 8));
    m = fmaxf(m, __shfl_xor_sync(FULL, m, 4));
    m = fmaxf(m, __shfl_xor_sync(FULL, m, 2));
    m = fmaxf(m, __shfl_xor_sync(FULL, m, 1));
    return m;
}
__device__ __forceinline__ float warp16_sum(float s) {
    s += __shfl_xor_sync(FULL, s, 8);
    s += __shfl_xor_sync(FULL, s, 4);
    s += __shfl_xor_sync(FULL, s, 2);
    s += __shfl_xor_sync(FULL, s, 1);
    return s;
}

// ---------------------------------------------------------------------------
// Pre-kernel: 4-d-group fp16 LUT. Block g covers d = 4g..4g+3.
// combo bits: y0..y3 in [0:4), p0..p3 in [4:8); c_k = (p_k<<1)|y_k.
// ---------------------------------------------------------------------------
__global__ void build_lut4(const float* __restrict__ py) {
    __shared__ float sT[4][4][16];      // [code][dk][h]
    const int g = blockIdx.x;
    const int tid = threadIdx.x;
    if (tid < 256) {
        int h = tid & 15;
        int dk = (tid >> 4) & 3;
        int c = tid >> 6;
        int d = g * 4 + dk;             // 22*4 = 88 exactly
        int yp = c >> 1, yb = c & 1;
        float p = py[(h * 2 + yp) * DD + d];
        sT[c][dk][h] = yb ? __logf(p) : __logf(1.0f - p);
    }
    __syncthreads();
    for (int e = tid; e < 256 * 16; e += blockDim.x) {
        int h = e & 15;
        int combo = e >> 4;
        int c0 = (((combo >> 4) & 1) << 1) | (combo & 1);
        int c1 = (((combo >> 5) & 1) << 1) | ((combo >> 1) & 1);
        int c2 = (((combo >> 6) & 1) << 1) | ((combo >> 2) & 1);
        int c3 = (((combo >> 7) & 1) << 1) | ((combo >> 3) & 1);
        float s = sT[c0][0][h] + sT[c1][1][h] + sT[c2][2][h] + sT[c3][3][h];
        g_LUTH[(g * 256 + combo) * 16 + h] = __float2half(s);
    }
}

// ---------------------------------------------------------------------------
__global__ void __launch_bounds__(1024, 1)
fused_hmm(const float* __restrict__ seq, const int* __restrict__ lengths,
          const float* __restrict__ px, float* __restrict__ out) {
    extern __shared__ __align__(16) unsigned smemw[];
    unsigned* sLUT = smemw + OFF_LUT;                 // fp16 LUT as u32 words
    float*    sE   = reinterpret_cast<float*>(smemw + OFF_E);    // [q][t][16]
    float*    sMe  = reinterpret_cast<float*>(smemw + OFF_ME);   // [q][256]
    unsigned* sPack = smemw + OFF_PK;                 // [q][257][3]
    float*    sVW  = reinterpret_cast<float*>(smemw + OFF_VW);   // [q][16]
    float*    sCB  = reinterpret_cast<float*>(smemw + OFF_CB);
    float*    sCS  = reinterpret_cast<float*>(smemw + OFF_CS);

    const int tid  = threadIdx.x;
    const int lane = tid & 31;
    const int wid  = tid >> 5;          // 0..31

    if (tid < 3) { sPack[tid] = 0u; sPack[772 + tid] = 0u; }
    if (tid < 512) sMe[tid] = 0.f;      // me=0 for masked t

    // ---- copy fp16 LUT gmem -> smem: exactly 11264 uint4 = 11 per thread ----
    {
        const uint4* src = reinterpret_cast<const uint4*>(g_LUTH);
        uint4* dst = reinterpret_cast<uint4*>(sLUT);
#pragma unroll
        for (int rep = 0; rep < 11; rep++)
            dst[tid + rep * 1024] = __ldg(src + tid + rep * 1024);
    }

    // ---- ballot-free bit-pack for both batches (only t < L) ----
#pragma unroll
    for (int rep = 0; rep < 2; rep++) {
        int idx = tid + rep * 1024;
        if (idx < 2 * TT * 3) {
            int q = (idx >= TT * 3) ? 1 : 0;
            int r = idx - q * (TT * 3);
            int t = r / 3;
            int w = r - t * 3;
            int Lq = lengths[blockIdx.x * 2 + q];
            if (t < Lq) {
                const float* sb = seq + ((size_t)(blockIdx.x * 2 + q)) * TT * DD;
                const float4* src = reinterpret_cast<const float4*>(sb + t * DD + w * 32);
                float4 v0 = src[0], v1 = src[1], v2 = src[2];
                float4 v3 = src[3], v4 = src[4], v5 = src[5];
                unsigned bits = pack4(v0) | (pack4(v1) << 4) | (pack4(v2) << 8) |
                                (pack4(v3) << 12) | (pack4(v4) << 16) | (pack4(v5) << 20);
                if (w < 2) {
                    float4 v6 = src[6], v7 = src[7];
                    bits |= (pack4(v6) << 24) | (pack4(v7) << 28);
                }
                sPack[q * 772 + (t + 1) * 3 + w] = bits;
            }
        }
    }
    __syncthreads();

    // ---- emit: warp w covers batch q=w>>4, t in [(w&15)*16,+16);
    //      lane pair = one t, half = h-range (0: h0-7, 1: h8-15) ----
    {
        const int q = wid >> 4;
        const int k = lane >> 1;
        const int half = lane & 1;
        const int t = (wid & 15) * 16 + k;
        const int L = lengths[blockIdx.x * 2 + q];

        const unsigned* pk = &sPack[q * 772 + t * 3];   // rows t (yprev), t+1 (y)
        unsigned pw[3], yw[3];
        pw[0] = pk[0]; pw[1] = pk[1]; pw[2] = pk[2];
        yw[0] = pk[3]; yw[1] = pk[4]; yw[2] = pk[5];

        __half2 acc0 = __float2half2_rn(0.f), acc1 = acc0, acc2 = acc0, acc3 = acc0;

        // garbage combos for t>=L index valid LUT entries and are unused
#pragma unroll
        for (int g = 0; g < NG4; g++) {
            const int bit = 4 * g;
            const int wi = bit >> 5;
            const int sh = bit & 31;
            unsigned yb = (yw[wi] >> sh) & 15u;
            unsigned pb = (pw[wi] >> sh) & 15u;
            unsigned combo = yb | (pb << 4);
            const uint4 v = *reinterpret_cast<const uint4*>(
                sLUT + (g * 256 + combo) * 8 + half * 4);
            acc0 = __hadd2(acc0, *reinterpret_cast<const __half2*>(&v.x));
            acc1 = __hadd2(acc1, *reinterpret_cast<const __half2*>(&v.y));
            acc2 = __hadd2(acc2, *reinterpret_cast<const __half2*>(&v.z));
            acc3 = __hadd2(acc3, *reinterpret_cast<const __half2*>(&v.w));
        }

        // max over this half's 8 h, then over the lane pair (16 h)
        __half2 m2 = __hmax2(__hmax2(acc0, acc1), __hmax2(acc2, acc3));
        float2 mf2 = __half22float2(m2);
        float mf = fmaxf(mf2.x, mf2.y);
        mf = fmaxf(mf, __shfl_xor_sync(FULL, mf, 1));

        const __half2 mh = __float2half2_rn(mf);
        const __half2 l2 = __float2half2_rn(L2E);
        float4 e0, e1;
        {
            __half2 x; unsigned xu, eu; __half2 eh; float2 ef;
            x = __hmul2(__hsub2(acc0, mh), l2);
            xu = *reinterpret_cast<unsigned*>(&x);
            asm("ex2.approx.f16x2 %0, %1;" : "=r"(eu) : "r"(xu));
            eh = *reinterpret_cast<__half2*>(&eu); ef = __half22float2(eh);
            e0.x = ef.x; e0.y = ef.y;
            x = __hmul2(__hsub2(acc1, mh), l2);
            xu = *reinterpret_cast<unsigned*>(&x);
            asm("ex2.approx.f16x2 %0, %1;" : "=r"(eu) : "r"(xu));
            eh = *reinterpret_cast<__half2*>(&eu); ef = __half22float2(eh);
            e0.z = ef.x; e0.w = ef.y;
            x = __hmul2(__hsub2(acc2, mh), l2);
            xu = *reinterpret_cast<unsigned*>(&x);
            asm("ex2.approx.f16x2 %0, %1;" : "=r"(eu) : "r"(xu));
            eh = *reinterpret_cast<__half2*>(&eu); ef = __half22float2(eh);
            e1.x = ef.x; e1.y = ef.y;
            x = __hmul2(__hsub2(acc3, mh), l2);
            xu = *reinterpret_cast<unsigned*>(&x);
            asm("ex2.approx.f16x2 %0, %1;" : "=r"(eu) : "r"(xu));
            eh = *reinterpret_cast<__half2*>(&eu); ef = __half22float2(eh);
            e1.z = ef.x; e1.w = ef.y;
        }

        if (t < L) {
            float4* eo = reinterpret_cast<float4*>(sE + q * 4096 + t * 16 + half * 8);
            eo[0] = e0;
            eo[1] = e1;
            if (half == 0) sMe[q * 256 + t] = mf;
        }
    }
    __syncthreads();

    // ---- parallel me-sum: warps 4,5 (one per batch) ----
    if (wid == 4 || wid == 5) {
        const int q = wid - 4;
        float s = 0.f;
#pragma unroll
        for (int i = 0; i < 8; i++) s += sMe[q * 256 + i * 32 + lane];
        s += __shfl_xor_sync(FULL, s, 16);
        s = warp16_sum(s);
        if (lane == 0) sCS[q] = s;
        asm volatile("bar.sync %0, %1;" :: "r"(1 + q), "r"(96) : "memory");
    }

    // ---- bidirectional scan: warps 0..3 = (batch q = wid>>1, dir = wid&1) ----
    if (wid < 4) {
        const int q = wid >> 1;
        const int dir = wid & 1;
        const int bGlob = blockIdx.x * 2 + q;
        const int L = lengths[bGlob];
        const int mid = L >> 1;
        const int j = lane & 15;
        const int hb = (lane >> 4) * 8;
        const float* sEq = sE + q * 4096;

        if (dir == 0) {
            // forward: u = alpha0^T prod_{t<mid} P diag(e_t)
            float Pc[8];
#pragma unroll
            for (int i = 0; i < 8; i++) Pc[i] = px[(hb + i) * 16 + j];

            float a = (j == 0) ? 1.f : 0.f;
            float C = 0.f;

            float ec = sEq[j];
            for (int t = 0; t < mid; t++) {
                float ecn = sEq[(t + 1) * 16 + j];   // always in-bounds
                float a0 = 0.f, a1 = 0.f;
#pragma unroll
                for (int i = 0; i < 8; i += 2) {
                    a0 = fmaf(__shfl_sync(FULL, a, hb + i),     Pc[i],     a0);
                    a1 = fmaf(__shfl_sync(FULL, a, hb + i + 1), Pc[i + 1], a1);
                }
                float s = a0 + a1;
                s += __shfl_xor_sync(FULL, s, 16);
                a = s * ec;
                if ((t & 15) == 15) {
                    float m = warp16_max(a);
                    a = __fdividef(a, m);
                    C += __logf(m);
                }
                ec = ecn;
            }

            asm volatile("bar.sync %0, %1;" :: "r"(1 + q), "r"(96) : "memory");

            float dv = warp16_sum(a * sVW[q * 16 + j]);
            float res = sCS[q] + C + sCB[q] + logf(dv) + (float)(TT - L) * LOG16F;

            // ---- in-kernel deterministic final reduction (last result) ----
            unsigned lastFlag = 0;
            if (lane == 0) {
                g_part[bGlob] = res;
                __threadfence();
                unsigned old = atomicInc(&g_ticket, BB - 1);   // wraps at 255
                lastFlag = (old == BB - 1) ? 1u : 0u;
            }
            lastFlag = __shfl_sync(FULL, lastFlag, 0);
            if (lastFlag) {
                __threadfence();
                float s2 = 0.f;
#pragma unroll
                for (int i = 0; i < BB / 32; i++)
                    s2 += *((volatile float*)&g_part[i * 32 + lane]);
                s2 += __shfl_xor_sync(FULL, s2, 16);
                s2 += __shfl_xor_sync(FULL, s2, 8);
                s2 += __shfl_xor_sync(FULL, s2, 4);
                s2 += __shfl_xor_sync(FULL, s2, 2);
                s2 += __shfl_xor_sync(FULL, s2, 1);
                if (lane == 0) out[0] = s2;
            }
        } else {
            // backward: w = prod_{t>=mid} (P diag(e_t)) * ones, descending
            float Pr[8];
#pragma unroll
            for (int i = 0; i < 8; i++) Pr[i] = px[j * 16 + hb + i];

            float w = 1.f;
            float C = 0.f;
            int cnt = 0;

            float ec = sEq[(L - 1) * 16 + j];
            for (int t = L - 1; t >= mid; t--) {
                float ecn = sEq[(t - 1) * 16 + j];   // in-bounds (mid >= 64)
                float sv = w * ec;
                float a0 = 0.f, a1 = 0.f;
#pragma unroll
                for (int i = 0; i < 8; i += 2) {
                    a0 = fmaf(__shfl_sync(FULL, sv, hb + i),     Pr[i],     a0);
                    a1 = fmaf(__shfl_sync(FULL, sv, hb + i + 1), Pr[i + 1], a1);
                }
                float s = a0 + a1;
                s += __shfl_xor_sync(FULL, s, 16);
                w = s;
                cnt++;
                if ((cnt & 15) == 0) {              // shrink >= 0.006^16 >> FLT_MIN
                    float m = warp16_max(w);
                    w = __fdividef(w, m);
                    C += __logf(m);
                }
                ec = ecn;
            }
            if (lane < 16) sVW[q * 16 + lane] = w;
            if (lane == 0) sCB[q] = C;
            asm volatile("bar.sync %0, %1;" :: "r"(1 + q), "r"(96) : "memory");
        }
    }
}

extern "C" void kernel_launch(void* const* d_in, const int* in_sizes, int n_in,
                              void* d_out, int out_size) {
    const float* seq     = (const float*)d_in[0];  // (B,T,D) float32
    const int*   lengths = (const int*)  d_in[1];  // (B,)    int32
    const float* probs_x = (const float*)d_in[2];  // (H,H)   float32
    const float* probs_y = (const float*)d_in[3];  // (H,2,D) float32

    build_lut4<<<NG4, 1024>>>(probs_y);
    cudaFuncSetAttribute(fused_hmm, cudaFuncAttributeMaxDynamicSharedMemorySize, SMEM_BYTES);
    fused_hmm<<<BB / 2, 1024, SMEM_BYTES>>>(seq, lengths, probs_x, (float*)d_out);
}

// round 16
// speedup vs baseline: 1.4917x; 1.1648x over previous
#include <cuda_runtime.h>
#include <cuda_fp16.h>

#define BB 256
#define TT 256
#define HH 16
#define DD 88
#define NG4 22
#define L2E 1.4426950408889634f
#define LOG16F 2.7725887222397811f
#define FULL 0xffffffffu

// dynamic smem layout (32-bit word offsets)
#define OFF_LUT 0          // 22*256*8 = 45056 words (fp16 emit LUT)
#define OFF_E   45056      // bf16 e: 2*256*16 u16 = 4096 words
#define OFF_ME  49152      // 512 floats
#define OFF_PK  49664      // u32: 2*772 = 1544
#define OFF_SEG 51208      // 16 matrices * 16*17 floats = 4352
#define OFF_SC  55560      // 16 floats (per-segment scale logs)
#define OFF_CS  55576      // 2 floats (emit-max sums)
#define SMEM_WORDS 55578
#define SMEM_BYTES (SMEM_WORDS * 4)

__device__ __half g_LUTH[NG4 * 256 * 16];   // [g][combo][h], fp16
__device__ float g_part[BB];
__device__ unsigned int g_ticket;            // zero-init; wraps via atomicInc

// pack two f32 -> bf16x2 (lo first)
#define PACK_BF16X2(r, lo, hi) \
    asm("cvt.rn.bf16x2.f32 %0, %1, %2;" : "=r"(r) : "f"(hi), "f"(lo))
#define MUL_BF16X2(r, a, b) \
    asm("mul.bf16x2 %0, %1, %2;" : "=r"(r) : "r"(a), "r"(b))

__device__ __forceinline__ void mma_bf16(float4& D,
    unsigned a0, unsigned a1, unsigned a2, unsigned a3,
    unsigned b0, unsigned b1) {
    asm("mma.sync.aligned.m16n8k16.row.col.f32.bf16.bf16.f32 "
        "{%0,%1,%2,%3}, {%4,%5,%6,%7}, {%8,%9}, {%10,%11,%12,%13};"
        : "=f"(D.x), "=f"(D.y), "=f"(D.z), "=f"(D.w)
        : "r"(a0), "r"(a1), "r"(a2), "r"(a3), "r"(b0), "r"(b1),
          "f"(0.f), "f"(0.f), "f"(0.f), "f"(0.f));
}

__device__ __forceinline__ unsigned pack4(float4 v) {
    return (v.x > 0.5f ? 1u : 0u) | (v.y > 0.5f ? 2u : 0u) |
           (v.z > 0.5f ? 4u : 0u) | (v.w > 0.5f ? 8u : 0u);
}
__device__ __forceinline__ float warp16_sum(float s) {
    s += __shfl_xor_sync(FULL, s, 8);
    s += __shfl_xor_sync(FULL, s, 4);
    s += __shfl_xor_sync(FULL, s, 2);
    s += __shfl_xor_sync(FULL, s, 1);
    return s;
}

// ---------------------------------------------------------------------------
// Pre-kernel: 4-d-group fp16 emit LUT (unchanged from R15)
// ---------------------------------------------------------------------------
__global__ void build_lut4(const float* __restrict__ py) {
    __shared__ float sT[4][4][16];
    const int g = blockIdx.x;
    const int tid = threadIdx.x;
    if (tid < 256) {
        int h = tid & 15;
        int dk = (tid >> 4) & 3;
        int c = tid >> 6;
        int d = g * 4 + dk;
        int yp = c >> 1, yb = c & 1;
        float p = py[(h * 2 + yp) * DD + d];
        sT[c][dk][h] = yb ? __logf(p) : __logf(1.0f - p);
    }
    __syncthreads();
    for (int e = tid; e < 256 * 16; e += blockDim.x) {
        int h = e & 15;
        int combo = e >> 4;
        int c0 = (((combo >> 4) & 1) << 1) | (combo & 1);
        int c1 = (((combo >> 5) & 1) << 1) | ((combo >> 1) & 1);
        int c2 = (((combo >> 6) & 1) << 1) | ((combo >> 2) & 1);
        int c3 = (((combo >> 7) & 1) << 1) | ((combo >> 3) & 1);
        float s = sT[c0][0][h] + sT[c1][1][h] + sT[c2][2][h] + sT[c3][3][h];
        g_LUTH[(g * 256 + combo) * 16 + h] = __float2half(s);
    }
}

// ---------------------------------------------------------------------------
__global__ void __launch_bounds__(1024, 1)
fused_hmm(const float* __restrict__ seq, const int* __restrict__ lengths,
          const float* __restrict__ px, float* __restrict__ out) {
    extern __shared__ __align__(16) unsigned smemw[];
    unsigned* sLUT = smemw + OFF_LUT;
    unsigned short* sEH = reinterpret_cast<unsigned short*>(smemw + OFF_E);  // [q][t][16] bf16
    float*    sMe  = reinterpret_cast<float*>(smemw + OFF_ME);
    unsigned* sPack = smemw + OFF_PK;
    float*    sSEG = reinterpret_cast<float*>(smemw + OFF_SEG);  // [q*8+s][row][17]
    float*    sC   = reinterpret_cast<float*>(smemw + OFF_SC);
    float*    sCS  = reinterpret_cast<float*>(smemw + OFF_CS);

    const int tid  = threadIdx.x;
    const int lane = tid & 31;
    const int wid  = tid >> 5;

    if (tid < 3) { sPack[tid] = 0u; sPack[772 + tid] = 0u; }
    if (tid < 512) sMe[tid] = 0.f;

    // ---- copy fp16 LUT gmem -> smem ----
    {
        const uint4* src = reinterpret_cast<const uint4*>(g_LUTH);
        uint4* dst = reinterpret_cast<uint4*>(sLUT);
#pragma unroll
        for (int rep = 0; rep < 11; rep++)
            dst[tid + rep * 1024] = __ldg(src + tid + rep * 1024);
    }

    // ---- ballot-free bit-pack (only t < L) ----
#pragma unroll
    for (int rep = 0; rep < 2; rep++) {
        int idx = tid + rep * 1024;
        if (idx < 2 * TT * 3) {
            int q = (idx >= TT * 3) ? 1 : 0;
            int r = idx - q * (TT * 3);
            int t = r / 3;
            int w = r - t * 3;
            int Lq = lengths[blockIdx.x * 2 + q];
            if (t < Lq) {
                const float* sb = seq + ((size_t)(blockIdx.x * 2 + q)) * TT * DD;
                const float4* src = reinterpret_cast<const float4*>(sb + t * DD + w * 32);
                float4 v0 = src[0], v1 = src[1], v2 = src[2];
                float4 v3 = src[3], v4 = src[4], v5 = src[5];
                unsigned bits = pack4(v0) | (pack4(v1) << 4) | (pack4(v2) << 8) |
                                (pack4(v3) << 12) | (pack4(v4) << 16) | (pack4(v5) << 20);
                if (w < 2) {
                    float4 v6 = src[6], v7 = src[7];
                    bits |= (pack4(v6) << 24) | (pack4(v7) << 28);
                }
                sPack[q * 772 + (t + 1) * 3 + w] = bits;
            }
        }
    }
    __syncthreads();

    // ---- emit (R15 scheme, bf16 output): warp w: q=w>>4, t chunk w&15 ----
    {
        const int q = wid >> 4;
        const int k = lane >> 1;
        const int half = lane & 1;
        const int t = (wid & 15) * 16 + k;
        const int L = lengths[blockIdx.x * 2 + q];

        const unsigned* pk = &sPack[q * 772 + t * 3];
        unsigned pw[3], yw[3];
        pw[0] = pk[0]; pw[1] = pk[1]; pw[2] = pk[2];
        yw[0] = pk[3]; yw[1] = pk[4]; yw[2] = pk[5];

        __half2 acc0 = __float2half2_rn(0.f), acc1 = acc0, acc2 = acc0, acc3 = acc0;
#pragma unroll
        for (int g = 0; g < NG4; g++) {
            const int bit = 4 * g;
            const int wi = bit >> 5;
            const int sh = bit & 31;
            unsigned yb = (yw[wi] >> sh) & 15u;
            unsigned pb = (pw[wi] >> sh) & 15u;
            unsigned combo = yb | (pb << 4);
            const uint4 v = *reinterpret_cast<const uint4*>(
                sLUT + (g * 256 + combo) * 8 + half * 4);
            acc0 = __hadd2(acc0, *reinterpret_cast<const __half2*>(&v.x));
            acc1 = __hadd2(acc1, *reinterpret_cast<const __half2*>(&v.y));
            acc2 = __hadd2(acc2, *reinterpret_cast<const __half2*>(&v.z));
            acc3 = __hadd2(acc3, *reinterpret_cast<const __half2*>(&v.w));
        }

        __half2 m2 = __hmax2(__hmax2(acc0, acc1), __hmax2(acc2, acc3));
        float2 mf2 = __half22float2(m2);
        float mf = fmaxf(mf2.x, mf2.y);
        mf = fmaxf(mf, __shfl_xor_sync(FULL, mf, 1));

        const __half2 mh = __float2half2_rn(mf);
        const __half2 l2 = __float2half2_rn(L2E);
        float2 fA, fB, fC, fD;
        {
            __half2 x; unsigned xu, eu;
            x = __hmul2(__hsub2(acc0, mh), l2);
            xu = *reinterpret_cast<unsigned*>(&x);
            asm("ex2.approx.f16x2 %0, %1;" : "=r"(eu) : "r"(xu));
            fA = __half22float2(*reinterpret_cast<__half2*>(&eu));
            x = __hmul2(__hsub2(acc1, mh), l2);
            xu = *reinterpret_cast<unsigned*>(&x);
            asm("ex2.approx.f16x2 %0, %1;" : "=r"(eu) : "r"(xu));
            fB = __half22float2(*reinterpret_cast<__half2*>(&eu));
            x = __hmul2(__hsub2(acc2, mh), l2);
            xu = *reinterpret_cast<unsigned*>(&x);
            asm("ex2.approx.f16x2 %0, %1;" : "=r"(eu) : "r"(xu));
            fC = __half22float2(*reinterpret_cast<__half2*>(&eu));
            x = __hmul2(__hsub2(acc3, mh), l2);
            xu = *reinterpret_cast<unsigned*>(&x);
            asm("ex2.approx.f16x2 %0, %1;" : "=r"(eu) : "r"(xu));
            fD = __half22float2(*reinterpret_cast<__half2*>(&eu));
        }

        if (t < L) {
            unsigned w0, w1, w2, w3;
            PACK_BF16X2(w0, fA.x, fA.y);
            PACK_BF16X2(w1, fB.x, fB.y);
            PACK_BF16X2(w2, fC.x, fC.y);
            PACK_BF16X2(w3, fD.x, fD.y);
            uint4 st; st.x = w0; st.y = w1; st.z = w2; st.w = w3;
            *reinterpret_cast<uint4*>(smemw + OFF_E + q * 2048 + t * 8 + half * 4) = st;
            if (half == 0) sMe[q * 256 + t] = mf;
        }
    }
    __syncthreads();

    // ---- segment matrix products: warps 0-15 = (q = w>>3, s = w&7) ----
    if (wid < 16) {
        const int q = wid >> 3;
        const int s = wid & 7;
        const int L = lengths[blockIdx.x * 2 + q];
        const int seg = (L + 7) >> 3;
        const int t0 = s * seg;
        const int t1 = (t0 + seg < L) ? (t0 + seg) : L;
        const int g = lane >> 2;
        const int t2 = (lane & 3) * 2;

        // P fragments (B operand, col-major): b0 rows t2,t2+1; b1 rows t2+8,+9
        unsigned pfA0, pfA1, pfB0, pfB1;
        PACK_BF16X2(pfA0, px[t2 * 16 + g],           px[(t2 + 1) * 16 + g]);
        PACK_BF16X2(pfA1, px[(t2 + 8) * 16 + g],     px[(t2 + 9) * 16 + g]);
        PACK_BF16X2(pfB0, px[t2 * 16 + g + 8],       px[(t2 + 1) * 16 + g + 8]);
        PACK_BF16X2(pfB1, px[(t2 + 8) * 16 + g + 8], px[(t2 + 9) * 16 + g + 8]);

        unsigned idA;
        PACK_BF16X2(idA, (g == t2) ? 1.f : 0.f, (g == t2 + 1) ? 1.f : 0.f);
        unsigned a0 = idA, a1 = 0u, a2 = 0u, a3 = idA;
        float C = 0.f;
        float4 D0, D1;

        const unsigned short* eb = sEH + q * 4096;
        for (int t = t0; t < t1; t++) {
            unsigned e0 = eb[t * 16 + g];
            unsigned e1 = eb[t * 16 + 8 + g];
            e0 *= 0x10001u;                  // broadcast bf16 into both halves
            e1 *= 0x10001u;
            unsigned b00, b01, b10, b11;
            MUL_BF16X2(b00, pfA0, e0);
            MUL_BF16X2(b01, pfA1, e0);
            MUL_BF16X2(b10, pfB0, e1);
            MUL_BF16X2(b11, pfB1, e1);
            mma_bf16(D0, a0, a1, a2, a3, b00, b01);
            mma_bf16(D1, a0, a1, a2, a3, b10, b11);

            if ((((t - t0) & 7) == 7) || (t == t1 - 1)) {
                float m = fmaxf(fmaxf(fmaxf(D0.x, D0.y), fmaxf(D0.z, D0.w)),
                                fmaxf(fmaxf(D1.x, D1.y), fmaxf(D1.z, D1.w)));
                m = fmaxf(m, __shfl_xor_sync(FULL, m, 16));
                m = fmaxf(m, __shfl_xor_sync(FULL, m, 8));
                m = fmaxf(m, __shfl_xor_sync(FULL, m, 4));
                m = fmaxf(m, __shfl_xor_sync(FULL, m, 2));
                m = fmaxf(m, __shfl_xor_sync(FULL, m, 1));
                float r = __fdividef(1.f, m);
                D0.x *= r; D0.y *= r; D0.z *= r; D0.w *= r;
                D1.x *= r; D1.y *= r; D1.z *= r; D1.w *= r;
                C += __logf(m);
            }
            PACK_BF16X2(a0, D0.x, D0.y);
            PACK_BF16X2(a1, D0.z, D0.w);
            PACK_BF16X2(a2, D1.x, D1.y);
            PACK_BF16X2(a3, D1.z, D1.w);
        }
        // store f32 matrix (max-normalized) + scale
        float* Sm = sSEG + (q * 8 + s) * 272;
        Sm[g * 17 + t2]           = D0.x;
        Sm[g * 17 + t2 + 1]       = D0.y;
        Sm[(g + 8) * 17 + t2]     = D0.z;
        Sm[(g + 8) * 17 + t2 + 1] = D0.w;
        Sm[g * 17 + t2 + 8]       = D1.x;
        Sm[g * 17 + t2 + 9]       = D1.y;
        Sm[(g + 8) * 17 + t2 + 8] = D1.z;
        Sm[(g + 8) * 17 + t2 + 9] = D1.w;
        if (lane == 0) sC[q * 8 + s] = C;
    }

    // ---- parallel me-sum: warps 16,17 ----
    if (wid == 16 || wid == 17) {
        const int q = wid - 16;
        float s = 0.f;
#pragma unroll
        for (int i = 0; i < 8; i++) s += sMe[q * 256 + i * 32 + lane];
        s += __shfl_xor_sync(FULL, s, 16);
        s = warp16_sum(s);
        if (lane == 0) sCS[q] = s;
    }
    __syncthreads();

    // ---- combine: warps 0,1 chain the 8 segment matrices and finish ----
    if (wid < 2) {
        const int q = wid;
        const int bGlob = blockIdx.x * 2 + q;
        const int L = lengths[bGlob];
        const int g = lane >> 2;
        const int t2 = (lane & 3) * 2;

        unsigned idA;
        PACK_BF16X2(idA, (g == t2) ? 1.f : 0.f, (g == t2 + 1) ? 1.f : 0.f);
        unsigned a0 = idA, a1 = 0u, a2 = 0u, a3 = idA;
        float4 D0, D1;

        const float* Sm = sSEG + q * 8 * 272;
#pragma unroll
        for (int s = 0; s < 8; s++) {
            const float* S = Sm + s * 272;
            unsigned b00, b01, b10, b11;
            PACK_BF16X2(b00, S[t2 * 17 + g],           S[(t2 + 1) * 17 + g]);
            PACK_BF16X2(b01, S[(t2 + 8) * 17 + g],     S[(t2 + 9) * 17 + g]);
            PACK_BF16X2(b10, S[t2 * 17 + g + 8],       S[(t2 + 1) * 17 + g + 8]);
            PACK_BF16X2(b11, S[(t2 + 8) * 17 + g + 8], S[(t2 + 9) * 17 + g + 8]);
            mma_bf16(D0, a0, a1, a2, a3, b00, b01);
            mma_bf16(D1, a0, a1, a2, a3, b10, b11);
            if (s < 7) {
                PACK_BF16X2(a0, D0.x, D0.y);
                PACK_BF16X2(a1, D0.z, D0.w);
                PACK_BF16X2(a2, D1.x, D1.y);
                PACK_BF16X2(a3, D1.z, D1.w);
            }
        }

        float Cc = (lane < 8) ? sC[q * 8 + lane] : 0.f;
        Cc = warp16_sum(Cc);

        // row 0 of the full product: lanes with g==0 hold it
        float val = (g == 0) ? ((D0.x + D0.y) + (D1.x + D1.y)) : 0.f;
        val += __shfl_xor_sync(FULL, val, 1);
        val += __shfl_xor_sync(FULL, val, 2);

        float res = Cc + logf(val) + sCS[q] + (float)(TT - L) * LOG16F;

        // ---- in-kernel deterministic final reduction (last result) ----
        unsigned lastFlag = 0;
        if (lane == 0) {
            g_part[bGlob] = res;
            __threadfence();
            unsigned old = atomicInc(&g_ticket, BB - 1);
            lastFlag = (old == BB - 1) ? 1u : 0u;
        }
        lastFlag = __shfl_sync(FULL, lastFlag, 0);
        if (lastFlag) {
            __threadfence();
            float s2 = 0.f;
#pragma unroll
            for (int i = 0; i < BB / 32; i++)
                s2 += *((volatile float*)&g_part[i * 32 + lane]);
            s2 += __shfl_xor_sync(FULL, s2, 16);
            s2 += __shfl_xor_sync(FULL, s2, 8);
            s2 += __shfl_xor_sync(FULL, s2, 4);
            s2 += __shfl_xor_sync(FULL, s2, 2);
            s2 += __shfl_xor_sync(FULL, s2, 1);
            if (lane == 0) out[0] = s2;
        }
    }
}

extern "C" void kernel_launch(void* const* d_in, const int* in_sizes, int n_in,
                              void* d_out, int out_size) {
    const float* seq     = (const float*)d_in[0];  // (B,T,D) float32
    const int*   lengths = (const int*)  d_in[1];  // (B,)    int32
    const float* probs_x = (const float*)d_in[2];  // (H,H)   float32
    const float* probs_y = (const float*)d_in[3];  // (H,2,D) float32

    build_lut4<<<NG4, 1024>>>(probs_y);
    cudaFuncSetAttribute(fused_hmm, cudaFuncAttributeMaxDynamicSharedMemorySize, SMEM_BYTES);
    fused_hmm<<<BB / 2, 1024, SMEM_BYTES>>>(seq, lengths, probs_x, (float*)d_out);
}

// round 17
// speedup vs baseline: 1.6200x; 1.0860x over previous
#include <cuda_runtime.h>
#include <cuda_fp16.h>

#define BB 256
#define TT 256
#define HH 16
#define DD 88
#define NG3 30
#define L2E 1.4426950408889634f
#define LOG16F 2.7725887222397811f
#define FULL 0xffffffffu

// dynamic smem layout (32-bit word offsets)
#define OFF_LUT 0          // 30*64*8 = 15360 words (fp16 3-d LUT, 61.4 KB)
#define OFF_W   15360      // 5632 floats: base log table [c][d][h]
#define OFF_E   20992      // bf16 e: 2*256*16 u16 = 4096 words
#define OFF_ME  25088      // 512 floats
#define OFF_PK  25600      // u32: 2*772 = 1544
#define OFF_SEG 27144      // 16 matrices * 16*17 floats = 4352
#define OFF_SC  31496      // 16 floats
#define OFF_CS  31512      // 2 floats
#define SMEM_WORDS 31514
#define SMEM_BYTES (SMEM_WORDS * 4)

__device__ float g_part[BB];
__device__ unsigned int g_ticket;            // zero-init; wraps via atomicInc

#define PACK_BF16X2(r, lo, hi) \
    asm("cvt.rn.bf16x2.f32 %0, %1, %2;" : "=r"(r) : "f"(hi), "f"(lo))
#define MUL_BF16X2(r, a, b) \
    asm("mul.bf16x2 %0, %1, %2;" : "=r"(r) : "r"(a), "r"(b))

__device__ __forceinline__ void mma_bf16(float4& D,
    unsigned a0, unsigned a1, unsigned a2, unsigned a3,
    unsigned b0, unsigned b1) {
    asm("mma.sync.aligned.m16n8k16.row.col.f32.bf16.bf16.f32 "
        "{%0,%1,%2,%3}, {%4,%5,%6,%7}, {%8,%9}, {%10,%11,%12,%13};"
        : "=f"(D.x), "=f"(D.y), "=f"(D.z), "=f"(D.w)
        : "r"(a0), "r"(a1), "r"(a2), "r"(a3), "r"(b0), "r"(b1),
          "f"(0.f), "f"(0.f), "f"(0.f), "f"(0.f));
}

__device__ __forceinline__ unsigned pack4(float4 v) {
    return (v.x > 0.5f ? 1u : 0u) | (v.y > 0.5f ? 2u : 0u) |
           (v.z > 0.5f ? 4u : 0u) | (v.w > 0.5f ? 8u : 0u);
}
__device__ __forceinline__ float warp16_sum(float s) {
    s += __shfl_xor_sync(FULL, s, 8);
    s += __shfl_xor_sync(FULL, s, 4);
    s += __shfl_xor_sync(FULL, s, 2);
    s += __shfl_xor_sync(FULL, s, 1);
    return s;
}

__global__ void __launch_bounds__(1024, 1)
fused_hmm(const float* __restrict__ seq, const int* __restrict__ lengths,
          const float* __restrict__ px, const float* __restrict__ py,
          float* __restrict__ out) {
    extern __shared__ __align__(16) unsigned smemw[];
    unsigned* sLUT = smemw + OFF_LUT;
    float*    sW   = reinterpret_cast<float*>(smemw + OFF_W);
    unsigned short* sEH = reinterpret_cast<unsigned short*>(smemw + OFF_E);
    float*    sMe  = reinterpret_cast<float*>(smemw + OFF_ME);
    unsigned* sPack = smemw + OFF_PK;
    float*    sSEG = reinterpret_cast<float*>(smemw + OFF_SEG);
    float*    sC   = reinterpret_cast<float*>(smemw + OFF_SC);
    float*    sCS  = reinterpret_cast<float*>(smemw + OFF_CS);

    const int tid  = threadIdx.x;
    const int lane = tid & 31;
    const int wid  = tid >> 5;

    if (tid < 3) { sPack[tid] = 0u; sPack[772 + tid] = 0u; }
    if (tid < 512) sMe[tid] = 0.f;

    // ---- phase 1a: base log table W[c][d][h] (5.5 logf per thread) ----
    for (int e = tid; e < 4 * DD * HH; e += 1024) {
        int h = e & 15;
        int rem = e >> 4;
        int d = rem % DD;
        int c = rem / DD;
        int yp = c >> 1, yb = c & 1;
        float p = py[(h * 2 + yp) * DD + d];
        sW[(c * DD + d) * 16 + h] = yb ? __logf(p) : __logf(1.0f - p);
    }

    // ---- phase 1b: ballot-free bit-pack (only t < L) ----
#pragma unroll
    for (int rep = 0; rep < 2; rep++) {
        int idx = tid + rep * 1024;
        if (idx < 2 * TT * 3) {
            int q = (idx >= TT * 3) ? 1 : 0;
            int r = idx - q * (TT * 3);
            int t = r / 3;
            int w = r - t * 3;
            int Lq = lengths[blockIdx.x * 2 + q];
            if (t < Lq) {
                const float* sb = seq + ((size_t)(blockIdx.x * 2 + q)) * TT * DD;
                const float4* src = reinterpret_cast<const float4*>(sb + t * DD + w * 32);
                float4 v0 = src[0], v1 = src[1], v2 = src[2];
                float4 v3 = src[3], v4 = src[4], v5 = src[5];
                unsigned bits = pack4(v0) | (pack4(v1) << 4) | (pack4(v2) << 8) |
                                (pack4(v3) << 12) | (pack4(v4) << 16) | (pack4(v5) << 20);
                if (w < 2) {
                    float4 v6 = src[6], v7 = src[7];
                    bits |= (pack4(v6) << 24) | (pack4(v7) << 28);
                }
                sPack[q * 772 + (t + 1) * 3 + w] = bits;
            }
        }
    }
    __syncthreads();

    // ---- phase 2: 3-d-group fp16 LUT: LUT[g][combo][h] = sum_k W[c_k][3g+k][h] ----
    for (int e = tid; e < NG3 * 64; e += 1024) {
        int combo = e & 63;
        int g = e >> 6;
        int c0 = (((combo >> 3) & 1) << 1) | (combo & 1);
        int c1 = (((combo >> 4) & 1) << 1) | ((combo >> 1) & 1);
        int c2 = (((combo >> 5) & 1) << 1) | ((combo >> 2) & 1);
        int d0 = 3 * g, d1 = 3 * g + 1, d2 = 3 * g + 2;
        const float4* w0 = reinterpret_cast<const float4*>(sW + (c0 * DD + d0) * 16);
        const float4* w1 = reinterpret_cast<const float4*>(sW + (c1 * DD + d1) * 16);
        const float4* w2 = reinterpret_cast<const float4*>(sW + (c2 * DD + d2) * 16);
        unsigned outw[8];
#pragma unroll
        for (int h4 = 0; h4 < 4; h4++) {
            float4 a = w0[h4];
            float4 s = a;
            if (d1 < DD) {
                float4 b = w1[h4];
                s.x += b.x; s.y += b.y; s.z += b.z; s.w += b.w;
            }
            if (d2 < DD) {
                float4 c = w2[h4];
                s.x += c.x; s.y += c.y; s.z += c.z; s.w += c.w;
            }
            __half2 p0 = __floats2half2_rn(s.x, s.y);
            __half2 p1 = __floats2half2_rn(s.z, s.w);
            outw[h4 * 2]     = *reinterpret_cast<unsigned*>(&p0);
            outw[h4 * 2 + 1] = *reinterpret_cast<unsigned*>(&p1);
        }
        uint4* dst = reinterpret_cast<uint4*>(sLUT + e * 8);
        dst[0] = make_uint4(outw[0], outw[1], outw[2], outw[3]);
        dst[1] = make_uint4(outw[4], outw[5], outw[6], outw[7]);
    }
    __syncthreads();

    // ---- emit: warp w: q=w>>4, t chunk w&15; lane pair = one t, half = h-range ----
    {
        const int q = wid >> 4;
        const int k = lane >> 1;
        const int half = lane & 1;
        const int t = (wid & 15) * 16 + k;
        const int L = lengths[blockIdx.x * 2 + q];

        const unsigned* pk = &sPack[q * 772 + t * 3];
        unsigned pw[4], yw[4];
        pw[0] = pk[0]; pw[1] = pk[1]; pw[2] = pk[2]; pw[3] = 0u;
        yw[0] = pk[3]; yw[1] = pk[4]; yw[2] = pk[5]; yw[3] = 0u;

        __half2 acc0 = __float2half2_rn(0.f), acc1 = acc0, acc2 = acc0, acc3 = acc0;
#pragma unroll
        for (int g = 0; g < NG3; g++) {
            const int bp = 3 * g;
            const int wi = bp >> 5;
            const int sh = bp & 31;
            unsigned yb = __funnelshift_r(yw[wi], yw[wi + 1], sh) & 7u;
            unsigned pb = __funnelshift_r(pw[wi], pw[wi + 1], sh) & 7u;
            unsigned combo = yb | (pb << 3);
            const uint4 v = *reinterpret_cast<const uint4*>(
                sLUT + (g * 64 + combo) * 8 + half * 4);
            acc0 = __hadd2(acc0, *reinterpret_cast<const __half2*>(&v.x));
            acc1 = __hadd2(acc1, *reinterpret_cast<const __half2*>(&v.y));
            acc2 = __hadd2(acc2, *reinterpret_cast<const __half2*>(&v.z));
            acc3 = __hadd2(acc3, *reinterpret_cast<const __half2*>(&v.w));
        }

        __half2 m2 = __hmax2(__hmax2(acc0, acc1), __hmax2(acc2, acc3));
        float2 mf2 = __half22float2(m2);
        float mf = fmaxf(mf2.x, mf2.y);
        mf = fmaxf(mf, __shfl_xor_sync(FULL, mf, 1));

        const __half2 mh = __float2half2_rn(mf);
        const __half2 l2 = __float2half2_rn(L2E);
        float2 fA, fB, fC, fD;
        {
            __half2 x; unsigned xu, eu;
            x = __hmul2(__hsub2(acc0, mh), l2);
            xu = *reinterpret_cast<unsigned*>(&x);
            asm("ex2.approx.f16x2 %0, %1;" : "=r"(eu) : "r"(xu));
            fA = __half22float2(*reinterpret_cast<__half2*>(&eu));
            x = __hmul2(__hsub2(acc1, mh), l2);
            xu = *reinterpret_cast<unsigned*>(&x);
            asm("ex2.approx.f16x2 %0, %1;" : "=r"(eu) : "r"(xu));
            fB = __half22float2(*reinterpret_cast<__half2*>(&eu));
            x = __hmul2(__hsub2(acc2, mh), l2);
            xu = *reinterpret_cast<unsigned*>(&x);
            asm("ex2.approx.f16x2 %0, %1;" : "=r"(eu) : "r"(xu));
            fC = __half22float2(*reinterpret_cast<__half2*>(&eu));
            x = __hmul2(__hsub2(acc3, mh), l2);
            xu = *reinterpret_cast<unsigned*>(&x);
            asm("ex2.approx.f16x2 %0, %1;" : "=r"(eu) : "r"(xu));
            fD = __half22float2(*reinterpret_cast<__half2*>(&eu));
        }

        if (t < L) {
            unsigned w0, w1, w2, w3;
            PACK_BF16X2(w0, fA.x, fA.y);
            PACK_BF16X2(w1, fB.x, fB.y);
            PACK_BF16X2(w2, fC.x, fC.y);
            PACK_BF16X2(w3, fD.x, fD.y);
            uint4 st; st.x = w0; st.y = w1; st.z = w2; st.w = w3;
            *reinterpret_cast<uint4*>(smemw + OFF_E + q * 2048 + t * 8 + half * 4) = st;
            if (half == 0) sMe[q * 256 + t] = mf;
        }
    }
    __syncthreads();

    // ---- segment matrix products: warps 0-15 = (q = w>>3, s = w&7) ----
    if (wid < 16) {
        const int q = wid >> 3;
        const int s = wid & 7;
        const int L = lengths[blockIdx.x * 2 + q];
        const int seg = (L + 7) >> 3;
        const int t0 = s * seg;
        const int t1 = (t0 + seg < L) ? (t0 + seg) : L;
        const int g = lane >> 2;
        const int t2 = (lane & 3) * 2;

        unsigned pfA0, pfA1, pfB0, pfB1;
        PACK_BF16X2(pfA0, px[t2 * 16 + g],           px[(t2 + 1) * 16 + g]);
        PACK_BF16X2(pfA1, px[(t2 + 8) * 16 + g],     px[(t2 + 9) * 16 + g]);
        PACK_BF16X2(pfB0, px[t2 * 16 + g + 8],       px[(t2 + 1) * 16 + g + 8]);
        PACK_BF16X2(pfB1, px[(t2 + 8) * 16 + g + 8], px[(t2 + 9) * 16 + g + 8]);

        unsigned idA;
        PACK_BF16X2(idA, (g == t2) ? 1.f : 0.f, (g == t2 + 1) ? 1.f : 0.f);
        unsigned a0 = idA, a1 = 0u, a2 = 0u, a3 = idA;
        float C = 0.f;
        float4 D0, D1;

        const unsigned short* eb = sEH + q * 4096;
        for (int t = t0; t < t1; t++) {
            unsigned e0 = eb[t * 16 + g];
            unsigned e1 = eb[t * 16 + 8 + g];
            e0 *= 0x10001u;
            e1 *= 0x10001u;
            unsigned b00, b01, b10, b11;
            MUL_BF16X2(b00, pfA0, e0);
            MUL_BF16X2(b01, pfA1, e0);
            MUL_BF16X2(b10, pfB0, e1);
            MUL_BF16X2(b11, pfB1, e1);
            mma_bf16(D0, a0, a1, a2, a3, b00, b01);
            mma_bf16(D1, a0, a1, a2, a3, b10, b11);

            if ((((t - t0) & 15) == 15) || (t == t1 - 1)) {
                float m = fmaxf(fmaxf(fmaxf(D0.x, D0.y), fmaxf(D0.z, D0.w)),
                                fmaxf(fmaxf(D1.x, D1.y), fmaxf(D1.z, D1.w)));
                m = fmaxf(m, __shfl_xor_sync(FULL, m, 16));
                m = fmaxf(m, __shfl_xor_sync(FULL, m, 8));
                m = fmaxf(m, __shfl_xor_sync(FULL, m, 4));
                m = fmaxf(m, __shfl_xor_sync(FULL, m, 2));
                m = fmaxf(m, __shfl_xor_sync(FULL, m, 1));
                float r = __fdividef(1.f, m);
                D0.x *= r; D0.y *= r; D0.z *= r; D0.w *= r;
                D1.x *= r; D1.y *= r; D1.z *= r; D1.w *= r;
                C += __logf(m);
            }
            PACK_BF16X2(a0, D0.x, D0.y);
            PACK_BF16X2(a1, D0.z, D0.w);
            PACK_BF16X2(a2, D1.x, D1.y);
            PACK_BF16X2(a3, D1.z, D1.w);
        }
        float* Sm = sSEG + (q * 8 + s) * 272;
        Sm[g * 17 + t2]           = D0.x;
        Sm[g * 17 + t2 + 1]       = D0.y;
        Sm[(g + 8) * 17 + t2]     = D0.z;
        Sm[(g + 8) * 17 + t2 + 1] = D0.w;
        Sm[g * 17 + t2 + 8]       = D1.x;
        Sm[g * 17 + t2 + 9]       = D1.y;
        Sm[(g + 8) * 17 + t2 + 8] = D1.z;
        Sm[(g + 8) * 17 + t2 + 9] = D1.w;
        if (lane == 0) sC[q * 8 + s] = C;
    }

    // ---- parallel me-sum: warps 16,17 (overlaps segment scan) ----
    if (wid == 16 || wid == 17) {
        const int q = wid - 16;
        float s = 0.f;
#pragma unroll
        for (int i = 0; i < 8; i++) s += sMe[q * 256 + i * 32 + lane];
        s += __shfl_xor_sync(FULL, s, 16);
        s = warp16_sum(s);
        if (lane == 0) sCS[q] = s;
    }
    __syncthreads();

    // ---- combine: warps 0,1 chain the 8 segment matrices and finish ----
    if (wid < 2) {
        const int q = wid;
        const int bGlob = blockIdx.x * 2 + q;
        const int L = lengths[bGlob];
        const int g = lane >> 2;
        const int t2 = (lane & 3) * 2;

        unsigned idA;
        PACK_BF16X2(idA, (g == t2) ? 1.f : 0.f, (g == t2 + 1) ? 1.f : 0.f);
        unsigned a0 = idA, a1 = 0u, a2 = 0u, a3 = idA;
        float4 D0, D1;

        const float* Sm = sSEG + q * 8 * 272;
#pragma unroll
        for (int s = 0; s < 8; s++) {
            const float* S = Sm + s * 272;
            unsigned b00, b01, b10, b11;
            PACK_BF16X2(b00, S[t2 * 17 + g],           S[(t2 + 1) * 17 + g]);
            PACK_BF16X2(b01, S[(t2 + 8) * 17 + g],     S[(t2 + 9) * 17 + g]);
            PACK_BF16X2(b10, S[t2 * 17 + g + 8],       S[(t2 + 1) * 17 + g + 8]);
            PACK_BF16X2(b11, S[(t2 + 8) * 17 + g + 8], S[(t2 + 9) * 17 + g + 8]);
            mma_bf16(D0, a0, a1, a2, a3, b00, b01);
            mma_bf16(D1, a0, a1, a2, a3, b10, b11);
            if (s < 7) {
                PACK_BF16X2(a0, D0.x, D0.y);
                PACK_BF16X2(a1, D0.z, D0.w);
                PACK_BF16X2(a2, D1.x, D1.y);
                PACK_BF16X2(a3, D1.z, D1.w);
            }
        }

        float Cc = (lane < 8) ? sC[q * 8 + lane] : 0.f;
        Cc = warp16_sum(Cc);

        float val = (g == 0) ? ((D0.x + D0.y) + (D1.x + D1.y)) : 0.f;
        val += __shfl_xor_sync(FULL, val, 1);
        val += __shfl_xor_sync(FULL, val, 2);

        float res = Cc + logf(val) + sCS[q] + (float)(TT - L) * LOG16F;

        unsigned lastFlag = 0;
        if (lane == 0) {
            g_part[bGlob] = res;
            __threadfence();
            unsigned old = atomicInc(&g_ticket, BB - 1);
            lastFlag = (old == BB - 1) ? 1u : 0u;
        }
        lastFlag = __shfl_sync(FULL, lastFlag, 0);
        if (lastFlag) {
            __threadfence();
            float s2 = 0.f;
#pragma unroll
            for (int i = 0; i < BB / 32; i++)
                s2 += *((volatile float*)&g_part[i * 32 + lane]);
            s2 += __shfl_xor_sync(FULL, s2, 16);
            s2 += __shfl_xor_sync(FULL, s2, 8);
            s2 += __shfl_xor_sync(FULL, s2, 4);
            s2 += __shfl_xor_sync(FULL, s2, 2);
            s2 += __shfl_xor_sync(FULL, s2, 1);
            if (lane == 0) out[0] = s2;
        }
    }
}

extern "C" void kernel_launch(void* const* d_in, const int* in_sizes, int n_in,
                              void* d_out, int out_size) {
    const float* seq     = (const float*)d_in[0];  // (B,T,D) float32
    const int*   lengths = (const int*)  d_in[1];  // (B,)    int32
    const float* probs_x = (const float*)d_in[2];  // (H,H)   float32
    const float* probs_y = (const float*)d_in[3];  // (H,2,D) float32

    cudaFuncSetAttribute(fused_hmm, cudaFuncAttributeMaxDynamicSharedMemorySize, SMEM_BYTES);
    fused_hmm<<<BB / 2, 1024, SMEM_BYTES>>>(seq, lengths, probs_x, probs_y, (float*)d_out);
}